// round 9
// baseline (speedup 1.0000x reference)
#include <cuda_runtime.h>
#include <math.h>
#include <stdint.h>

#define NTOK 8192
#define DDIM 1024
#define HDIM 2048
#define MDIM 64
#define EEXP 8
#define HHALF 1024
#define ECAP 8192
#define NASSIGN (NTOK * 2)
#define S2C_SPLIT 16
#define EXP_SPLIT 8

// tf32-rounded: [X(permK) | enc_W | s2c_W | We1 | We2 | c2s_W | dec_W]
#define RN_X   0UL
#define RN_EW  8388608UL
#define RN_SW  10485760UL
#define RN_W1  10616832UL
#define RN_W2  11141120UL
#define RN_CW  11665408UL
#define RN_DW  11796480UL
#define RN_TOT 13893632UL
__device__ float g_rnd[RN_TOT];

__device__ float g_part_s2c[(size_t)S2C_SPLIT * NTOK * MDIM];
__device__ float g_cont[(size_t)NTOK * MDIM];          // k-permuted
__device__ int   g_assign_e[NASSIGN];
__device__ float g_assign_w[NASSIGN];
__device__ int   g_count[EEXP];
__device__ int   g_bucket[EEXP * ECAP];
__device__ float g_part_exp[(size_t)EXP_SPLIT * NASSIGN * MDIM];
__device__ float g_outflat[(size_t)NTOK * MDIM];       // k-permuted
__device__ float g_spk_moe[(size_t)NTOK * HDIM];       // k-permuted
__device__ float g_decoded[(size_t)NTOK * DDIM];

__device__ __forceinline__ unsigned f2tf(float x) {
    unsigned u; asm("cvt.rna.tf32.f32 %0, %1;" : "=r"(u) : "f"(x)); return u;
}
__device__ __forceinline__ float rtf(float x) { return __uint_as_float(f2tf(x)); }
__device__ __forceinline__ float sigf(float x) { return 1.0f / (1.0f + expf(-x)); }
// k -> permuted position within 8-group: [0,4,1,5,2,6,3,7]
__device__ __forceinline__ int permk(int k) {
    int j = k & 7;
    return (k & ~7) | ((j < 4) ? (j << 1) : (((j - 4) << 1) | 1));
}
__device__ __forceinline__ void cp16(void* dst, const void* src) {
    unsigned d = (unsigned)__cvta_generic_to_shared(dst);
    asm volatile("cp.async.cg.shared.global [%0], [%1], 16;\n" :: "r"(d), "l"(src));
}
__device__ __forceinline__ void cp_commit() { asm volatile("cp.async.commit_group;\n"); }
template<int N> __device__ __forceinline__ void cp_wait() {
    asm volatile("cp.async.wait_group %0;\n" :: "n"(N));
}
__device__ __forceinline__ void mma_tf32(float c[4], const unsigned a[4], const unsigned b[2]) {
    asm volatile(
        "mma.sync.aligned.m16n8k8.row.col.f32.tf32.tf32.f32 "
        "{%0,%1,%2,%3}, {%4,%5,%6,%7}, {%8,%9}, {%0,%1,%2,%3};\n"
        : "+f"(c[0]), "+f"(c[1]), "+f"(c[2]), "+f"(c[3])
        : "r"(a[0]), "r"(a[1]), "r"(a[2]), "r"(a[3]), "r"(b[0]), "r"(b[1]));
}

// fused (enc/expert) geometry: BK16, 4 stages. A [m][k-perm] stride 20, B [k][n] stride 136.
#define BM 128
#define BN 128
#define AS 20
#define BS1 136
#define STAGES 4
#define PIPE_FLOATS (STAGES * (BM * AS + 16 * BS1))   // 18944
#define SPIKE_S 136                                    // conflict-free LDS.64
#define W2_S 72
#define W2_OFF PIPE_FLOATS
#define FUSED_SMEM ((PIPE_FLOATS + 128 * W2_S) * 4)    // 112640 B

// plain (c2s/dec) geometry: BK32, 3 stages. A stride 40 (conflict-free LDS.64), B stride 136.
#define AS2 40
#define BS2 136
#define ST2 3
#define PIPE2_SMEM (ST2 * (BM * AS2 + 32 * BS2) * 4)   // 113664 B

// ---------------------------------------------------------------------------
// Pre-round to tf32 (rna); X gets k-permuted columns; zero counts.
// ---------------------------------------------------------------------------
__global__ void round_all(const float* __restrict__ X,   const float* __restrict__ encW,
                          const float* __restrict__ s2cW, const float* __restrict__ We1,
                          const float* __restrict__ We2,  const float* __restrict__ c2sW,
                          const float* __restrict__ decW)
{
    if (blockIdx.x == 0 && threadIdx.x < EEXP) g_count[threadIdx.x] = 0;
    const size_t f = ((size_t)blockIdx.x * 256 + threadIdx.x) * 4;
    if (f >= RN_TOT) return;
    if (f < RN_EW) {
        // X: permute the d index (within 8-groups). f 4-aligned:
        float4 v = *(const float4*)&X[f];
        const size_t base = f & ~7UL;
        const size_t rel  = (f & 4) ? 1 : 0;
        g_rnd[base + rel + 0] = rtf(v.x);
        g_rnd[base + rel + 2] = rtf(v.y);
        g_rnd[base + rel + 4] = rtf(v.z);
        g_rnd[base + rel + 6] = rtf(v.w);
        return;
    }
    const float* src; size_t off;
    if      (f < RN_SW) { src = encW; off = f - RN_EW; }
    else if (f < RN_W1) { src = s2cW; off = f - RN_SW; }
    else if (f < RN_W2) { src = We1;  off = f - RN_W1; }
    else if (f < RN_CW) { src = We2;  off = f - RN_W2; }
    else if (f < RN_DW) { src = c2sW; off = f - RN_CW; }
    else                { src = decW; off = f - RN_DW; }
    float4 v = *(const float4*)&src[off];
    v.x = rtf(v.x); v.y = rtf(v.y); v.z = rtf(v.z); v.w = rtf(v.w);
    *(float4*)&g_rnd[f] = v;
}

// ---------------------------------------------------------------------------
// Fused GEMM+GEMM (A k-permuted -> LDS.64 fragments; B [k][n] unchanged).
//   EXPM=false: enc+s2c.   EXPM=true: expert MLP (gather/scatter).
// ---------------------------------------------------------------------------
template<bool EXPM>
__global__ __launch_bounds__(256, 2)
void fused_gemm2(const float* __restrict__ A, const float* __restrict__ W1,
                 const float* __restrict__ b1, const float* __restrict__ W2,
                 float* __restrict__ Cpart, int K, int lda, int ldw1,
                 const int* __restrict__ bucket, const int* __restrict__ count)
{
    extern __shared__ float sm[];
    float* spike = sm;
    float* w2s   = sm + W2_OFF;

    const int tid = threadIdx.x, lane = tid & 31, w = tid >> 5;
    const int g = lane >> 2, tg = lane & 3;
    const int wm = w >> 2, wn = w & 3;
    const int bm0 = blockIdx.y * BM, bn0 = blockIdx.x * BN;
    const int e = EXPM ? blockIdx.z : 0;

    int cnt = 0;
    if (EXPM) {
        cnt = count[e];
        if (bm0 >= cnt) return;
    }

    const float* W1p = EXPM ? W1 + (size_t)e * MDIM * HHALF : W1;
    const float* b1p = EXPM ? b1 + (size_t)e * HHALF : b1;
    const float* W2p = EXPM ? W2 + (size_t)e * HHALF * MDIM : W2;

    constexpr int ALD = (BM * 16) / (256 * 4);
    size_t aoff[ALD];
#pragma unroll
    for (int it = 0; it < ALD; it++) {
        int idx = tid + it * 256;
        int r = idx >> 2;
        int grow = bm0 + r;
        if (EXPM) {
            int rr = (grow < cnt) ? grow : (cnt - 1);
            aoff[it] = (size_t)(bucket[e * ECAP + rr] >> 1) * MDIM;
        } else {
            aoff[it] = (size_t)grow * lda;
        }
    }

#pragma unroll
    for (int it = 0; it < (128 * 64) / (256 * 4); it++) {
        int idx = tid + it * 256;
        int r = idx >> 4, c4 = idx & 15;
        cp16(&w2s[r * W2_S + c4 * 4], &W2p[(size_t)(bn0 + r) * MDIM + c4 * 4]);
    }
    cp_commit();

    float c[4][4][4];
#pragma unroll
    for (int i = 0; i < 4; i++)
#pragma unroll
        for (int j = 0; j < 4; j++)
#pragma unroll
            for (int q = 0; q < 4; q++) c[i][j][q] = 0.0f;

    const int nk = K / 16;
    auto issue = [&](int st, int kt) {
        const int k0 = kt * 16;
        float* as = sm + st * (BM * AS);
        float* bs = sm + STAGES * (BM * AS) + st * (16 * BS1);
#pragma unroll
        for (int it = 0; it < ALD; it++) {
            int idx = tid + it * 256;
            int r = idx >> 2, c4 = idx & 3;
            cp16(&as[r * AS + c4 * 4], A + aoff[it] + k0 + c4 * 4);
        }
#pragma unroll
        for (int it = 0; it < (16 * BN) / (256 * 4); it++) {
            int idx = tid + it * 256;
            int r = idx >> 5, c4 = idx & 31;
            cp16(&bs[r * BS1 + c4 * 4], &W1p[(size_t)(k0 + r) * ldw1 + bn0 + c4 * 4]);
        }
    };

#pragma unroll
    for (int s = 0; s < STAGES - 1; s++) {
        if (s < nk) issue(s, s);
        cp_commit();
    }
    for (int kt = 0; kt < nk; kt++) {
        cp_wait<STAGES - 2>();
        __syncthreads();
        const int st = kt % STAGES;
        const float* as = sm + st * (BM * AS);
        const float* bs = sm + STAGES * (BM * AS) + st * (16 * BS1);
#pragma unroll
        for (int ks = 0; ks < 2; ks++) {
            unsigned a[4][4], b[4][2];
#pragma unroll
            for (int mf = 0; mf < 4; mf++) {
                const int m0 = wm * 64 + mf * 16;
                float2 lo = *(const float2*)&as[(m0 + g)     * AS + ks * 8 + 2 * tg];
                float2 hi = *(const float2*)&as[(m0 + g + 8) * AS + ks * 8 + 2 * tg];
                a[mf][0] = __float_as_uint(lo.x);
                a[mf][1] = __float_as_uint(hi.x);
                a[mf][2] = __float_as_uint(lo.y);
                a[mf][3] = __float_as_uint(hi.y);
            }
#pragma unroll
            for (int nf = 0; nf < 4; nf++) {
                const int n0 = wn * 32 + nf * 8 + g;
                b[nf][0] = __float_as_uint(bs[(ks * 8 + tg)     * BS1 + n0]);
                b[nf][1] = __float_as_uint(bs[(ks * 8 + tg + 4) * BS1 + n0]);
            }
#pragma unroll
            for (int mf = 0; mf < 4; mf++)
#pragma unroll
                for (int nf = 0; nf < 4; nf++) mma_tf32(c[mf][nf], a[mf], b[nf]);
        }
        const int nxt = kt + STAGES - 1;
        if (nxt < nk) issue(nxt % STAGES, nxt);
        cp_commit();
    }

    cp_wait<0>();
    __syncthreads();
    // Activated tile -> smem spike, tf32-rounded, columns k-PERMUTED
#pragma unroll
    for (int mf = 0; mf < 4; mf++)
#pragma unroll
        for (int nf = 0; nf < 4; nf++) {
            const int col = wn * 32 + nf * 8 + 2 * tg;
            const int r0  = wm * 64 + mf * 16 + g;
#pragma unroll
            for (int h = 0; h < 2; h++) {
                const int row = r0 + h * 8;
                float v0 = c[mf][nf][h * 2 + 0] + b1p[bn0 + col];
                float v1 = c[mf][nf][h * 2 + 1] + b1p[bn0 + col + 1];
                if (EXPM) { v0 = fmaxf(v0, 0.0f); v1 = fmaxf(v1, 0.0f); }
                else      { v0 = sigf(v0);        v1 = sigf(v1); }
                spike[row * SPIKE_S + permk(col)]     = rtf(v0);
                spike[row * SPIKE_S + permk(col + 1)] = rtf(v1);
            }
        }
    __syncthreads();

    // mini GEMM: part[128x64] = spike(128x128, k-perm) @ w2s(128x64)
    const int wm2 = w >> 1, wn2 = w & 1;
    float c2[2][4][4];
#pragma unroll
    for (int i = 0; i < 2; i++)
#pragma unroll
        for (int j = 0; j < 4; j++)
#pragma unroll
            for (int q = 0; q < 4; q++) c2[i][j][q] = 0.0f;
#pragma unroll
    for (int ks = 0; ks < 16; ks++) {
        unsigned a[2][4], b[4][2];
#pragma unroll
        for (int mf = 0; mf < 2; mf++) {
            const int m0 = wm2 * 32 + mf * 16;
            float2 lo = *(const float2*)&spike[(m0 + g)     * SPIKE_S + ks * 8 + 2 * tg];
            float2 hi = *(const float2*)&spike[(m0 + g + 8) * SPIKE_S + ks * 8 + 2 * tg];
            a[mf][0] = __float_as_uint(lo.x);
            a[mf][1] = __float_as_uint(hi.x);
            a[mf][2] = __float_as_uint(lo.y);
            a[mf][3] = __float_as_uint(hi.y);
        }
#pragma unroll
        for (int nf = 0; nf < 4; nf++) {
            const int n0 = wn2 * 32 + nf * 8 + g;
            b[nf][0] = __float_as_uint(w2s[(ks * 8 + tg)     * W2_S + n0]);
            b[nf][1] = __float_as_uint(w2s[(ks * 8 + tg + 4) * W2_S + n0]);
        }
#pragma unroll
        for (int mf = 0; mf < 2; mf++)
#pragma unroll
            for (int nf = 0; nf < 4; nf++) mma_tf32(c2[mf][nf], a[mf], b[nf]);
    }
    const size_t sb = (size_t)blockIdx.x * (EXPM ? NASSIGN : NTOK) * MDIM;
#pragma unroll
    for (int mf = 0; mf < 2; mf++)
#pragma unroll
        for (int nf = 0; nf < 4; nf++) {
            const int col = wn2 * 32 + nf * 8 + 2 * tg;
            const int r0  = wm2 * 32 + mf * 16 + g;
#pragma unroll
            for (int h = 0; h < 2; h++) {
                const int row = r0 + h * 8;
                if (EXPM) {
                    if (bm0 + row < cnt) {
                        const int i = bucket[e * ECAP + bm0 + row];
                        *(float2*)&Cpart[sb + (size_t)i * MDIM + col] =
                            make_float2(c2[mf][nf][h * 2 + 0], c2[mf][nf][h * 2 + 1]);
                    }
                } else {
                    *(float2*)&Cpart[sb + (size_t)(bm0 + row) * MDIM + col] =
                        make_float2(c2[mf][nf][h * 2 + 0], c2[mf][nf][h * 2 + 1]);
                }
            }
        }
}

// ---------------------------------------------------------------------------
// Plain GEMM BK32, 3 stages. A k-permuted (stride 40, conflict-free LDS.64).
// MODE 0: decoder — sigmoid -> fp32 normal store.
// MODE 1: c2s    — sigmoid -> rtf, k-PERMUTED store (feeds decoder A).
// ---------------------------------------------------------------------------
template<int MODE>
__global__ __launch_bounds__(256, 2)
void mma_gemm(const float* __restrict__ A, const float* __restrict__ W,
              const float* __restrict__ bias, float* __restrict__ C,
              int K, int Hout)
{
    extern __shared__ float sm[];
    const int tid = threadIdx.x, lane = tid & 31, w = tid >> 5;
    const int g = lane >> 2, tg = lane & 3;
    const int wm = w >> 2, wn = w & 3;
    const int bm0 = blockIdx.y * BM, bn0 = blockIdx.x * BN;

    float c[4][4][4];
#pragma unroll
    for (int i = 0; i < 4; i++)
#pragma unroll
        for (int j = 0; j < 4; j++)
#pragma unroll
            for (int q = 0; q < 4; q++) c[i][j][q] = 0.0f;

    const int nk = K / 32;
    auto issue = [&](int st, int kt) {
        const int k0 = kt * 32;
        float* as = sm + st * (BM * AS2);
        float* bs = sm + ST2 * (BM * AS2) + st * (32 * BS2);
#pragma unroll
        for (int it = 0; it < (BM * 32) / (256 * 4); it++) {
            int idx = tid + it * 256;
            int r = idx >> 3, c4 = idx & 7;
            cp16(&as[r * AS2 + c4 * 4], &A[(size_t)(bm0 + r) * K + k0 + c4 * 4]);
        }
#pragma unroll
        for (int it = 0; it < (32 * BN) / (256 * 4); it++) {
            int idx = tid + it * 256;
            int r = idx >> 5, c4 = idx & 31;
            cp16(&bs[r * BS2 + c4 * 4], &W[(size_t)(k0 + r) * Hout + bn0 + c4 * 4]);
        }
    };

#pragma unroll
    for (int s = 0; s < ST2 - 1; s++) {
        if (s < nk) issue(s, s);
        cp_commit();
    }
    for (int kt = 0; kt < nk; kt++) {
        cp_wait<ST2 - 2>();
        __syncthreads();
        const int st = kt % ST2;
        const float* as = sm + st * (BM * AS2);
        const float* bs = sm + ST2 * (BM * AS2) + st * (32 * BS2);
#pragma unroll
        for (int ks = 0; ks < 4; ks++) {
            unsigned a[4][4], b[4][2];
#pragma unroll
            for (int mf = 0; mf < 4; mf++) {
                const int m0 = wm * 64 + mf * 16;
                float2 lo = *(const float2*)&as[(m0 + g)     * AS2 + ks * 8 + 2 * tg];
                float2 hi = *(const float2*)&as[(m0 + g + 8) * AS2 + ks * 8 + 2 * tg];
                a[mf][0] = __float_as_uint(lo.x);
                a[mf][1] = __float_as_uint(hi.x);
                a[mf][2] = __float_as_uint(lo.y);
                a[mf][3] = __float_as_uint(hi.y);
            }
#pragma unroll
            for (int nf = 0; nf < 4; nf++) {
                const int n0 = wn * 32 + nf * 8 + g;
                b[nf][0] = __float_as_uint(bs[(ks * 8 + tg)     * BS2 + n0]);
                b[nf][1] = __float_as_uint(bs[(ks * 8 + tg + 4) * BS2 + n0]);
            }
#pragma unroll
            for (int mf = 0; mf < 4; mf++)
#pragma unroll
                for (int nf = 0; nf < 4; nf++) mma_tf32(c[mf][nf], a[mf], b[nf]);
        }
        const int nxt = kt + ST2 - 1;
        if (nxt < nk) issue(nxt % ST2, nxt);
        cp_commit();
    }

#pragma unroll
    for (int mf = 0; mf < 4; mf++)
#pragma unroll
        for (int nf = 0; nf < 4; nf++) {
            const int col = bn0 + wn * 32 + nf * 8 + 2 * tg;
            const int r0  = bm0 + wm * 64 + mf * 16 + g;
#pragma unroll
            for (int h = 0; h < 2; h++) {
                const int row = r0 + h * 8;
                float v0 = sigf(c[mf][nf][h * 2 + 0] + bias[col]);
                float v1 = sigf(c[mf][nf][h * 2 + 1] + bias[col + 1]);
                if (MODE == 1) {
                    C[(size_t)row * Hout + permk(col)]     = rtf(v0);
                    C[(size_t)row * Hout + permk(col + 1)] = rtf(v1);
                } else {
                    *(float2*)&C[(size_t)row * Hout + col] = make_float2(v0, v1);
                }
            }
        }
}

// ---------------------------------------------------------------------------
__global__ void router_kernel(const float* __restrict__ part_s2c,
                              const float* __restrict__ s2c_b,
                              float* __restrict__ cont,
                              const float* __restrict__ rW1, const float* __restrict__ rb1,
                              const float* __restrict__ rW2, const float* __restrict__ rb2,
                              int* __restrict__ assign_e, float* __restrict__ assign_w)
{
    __shared__ float cs[64], hid[64], logit[8];
    const int n = blockIdx.x, t = threadIdx.x;

    float cv = s2c_b[t];
#pragma unroll
    for (int s = 0; s < S2C_SPLIT; s++)
        cv += part_s2c[(size_t)s * NTOK * MDIM + (size_t)n * MDIM + t];
    cont[(size_t)n * MDIM + permk(t)] = rtf(cv);   // expert A consumes permuted
    cs[t] = cv;
    __syncthreads();

    float a = rb1[t];
#pragma unroll
    for (int m = 0; m < 64; m++) a = fmaf(cs[m], rW1[m * 64 + t], a);
    hid[t] = tanhf(a);
    __syncthreads();

    if (t < EEXP) {
        float l = rb2[t];
#pragma unroll
        for (int j = 0; j < 64; j++) l = fmaf(hid[j], rW2[j * EEXP + t], l);
        logit[t] = l;
    }
    __syncthreads();

    if (t == 0) {
        float mx = logit[0];
        for (int e = 1; e < EEXP; e++) mx = fmaxf(mx, logit[e]);
        float p[EEXP];
        for (int e = 0; e < EEXP; e++) p[e] = expf(logit[e] - mx);
        int i1 = 0;
        for (int e = 1; e < EEXP; e++) if (p[e] > p[i1]) i1 = e;
        int i2 = (i1 == 0) ? 1 : 0;
        for (int e = 0; e < EEXP; e++) if (e != i1 && p[e] > p[i2]) i2 = e;
        const float denom = p[i1] + p[i2];
        const int ids[2] = {i1, i2};
        const float ws[2] = {p[i1] / denom, p[i2] / denom};
#pragma unroll
        for (int k = 0; k < 2; k++) {
            const int i = n * 2 + k;
            assign_e[i] = ids[k];
            assign_w[i] = ws[k];
            const int slot = atomicAdd(&g_count[ids[k]], 1);
            g_bucket[ids[k] * ECAP + slot] = i;
        }
    }
}

__global__ void combine_kernel(const float* __restrict__ part_exp,
                               const int* __restrict__ ae, const float* __restrict__ aw,
                               const float* __restrict__ be2, float* __restrict__ outflat)
{
    const int i = blockIdx.x * 256 + threadIdx.x;
    const int n = i >> 6, m = i & 63;
    float acc = 0.0f;
#pragma unroll
    for (int k = 0; k < 2; k++) {
        const int idx = 2 * n + k;
        float s = be2[ae[idx] * MDIM + m];
#pragma unroll
        for (int sp = 0; sp < EXP_SPLIT; sp++)
            s += part_exp[(size_t)sp * NASSIGN * MDIM + (size_t)idx * MDIM + m];
        acc = fmaf(aw[idx], s, acc);
    }
    outflat[(n << 6) + permk(m)] = rtf(acc);   // c2s A consumes permuted
}

__global__ void layernorm_kernel(const float* __restrict__ x,
                                 const float* __restrict__ g, const float* __restrict__ b,
                                 float* __restrict__ out)
{
    const int n = blockIdx.x, t = threadIdx.x;
    const float* row = x + (size_t)n * DDIM;
    float v[4];
    float s = 0.0f, s2 = 0.0f;
#pragma unroll
    for (int i = 0; i < 4; i++) {
        v[i] = row[t + i * 256];
        s += v[i]; s2 += v[i] * v[i];
    }
#pragma unroll
    for (int o = 16; o > 0; o >>= 1) {
        s  += __shfl_xor_sync(0xFFFFFFFFu, s, o);
        s2 += __shfl_xor_sync(0xFFFFFFFFu, s2, o);
    }
    __shared__ float sh1[8], sh2[8], mu_s, rstd_s;
    const int warp = t >> 5, lane = t & 31;
    if (lane == 0) { sh1[warp] = s; sh2[warp] = s2; }
    __syncthreads();
    if (t == 0) {
        float S = 0.0f, S2 = 0.0f;
        for (int wq = 0; wq < 8; wq++) { S += sh1[wq]; S2 += sh2[wq]; }
        float mu = S / (float)DDIM;
        mu_s = mu;
        rstd_s = rsqrtf(S2 / (float)DDIM - mu * mu + 1e-5f);
    }
    __syncthreads();
    const float mu = mu_s, rstd = rstd_s;
    float* orow = out + (size_t)n * DDIM;
#pragma unroll
    for (int i = 0; i < 4; i++) {
        int col = t + i * 256;
        orow[col] = (v[i] - mu) * rstd * g[col] + b[col];
    }
}

// ---------------------------------------------------------------------------
extern "C" void kernel_launch(void* const* d_in, const int* in_sizes, int n_in,
                              void* d_out, int out_size)
{
    const float* X     = (const float*)d_in[0];
    const float* enc_W = (const float*)d_in[1];
    const float* enc_b = (const float*)d_in[2];
    const float* s2c_W = (const float*)d_in[3];
    const float* s2c_b = (const float*)d_in[4];
    const float* rW1   = (const float*)d_in[5];
    const float* rb1   = (const float*)d_in[6];
    const float* rW2   = (const float*)d_in[7];
    const float* rb2   = (const float*)d_in[8];
    const float* We1   = (const float*)d_in[9];
    const float* be1   = (const float*)d_in[10];
    const float* We2   = (const float*)d_in[11];
    const float* be2   = (const float*)d_in[12];
    const float* c2s_W = (const float*)d_in[13];
    const float* c2s_b = (const float*)d_in[14];
    const float* dec_W = (const float*)d_in[15];
    const float* dec_b = (const float*)d_in[16];
    const float* ln_g  = (const float*)d_in[17];
    const float* ln_b  = (const float*)d_in[18];

    float *rnd, *part_s2c, *cont, *aw, *part_exp, *outflat, *spk_moe, *decoded;
    int *ae, *bucket, *count;
    cudaGetSymbolAddress((void**)&rnd,      g_rnd);
    cudaGetSymbolAddress((void**)&part_s2c, g_part_s2c);
    cudaGetSymbolAddress((void**)&cont,     g_cont);
    cudaGetSymbolAddress((void**)&ae,       g_assign_e);
    cudaGetSymbolAddress((void**)&aw,       g_assign_w);
    cudaGetSymbolAddress((void**)&count,    g_count);
    cudaGetSymbolAddress((void**)&bucket,   g_bucket);
    cudaGetSymbolAddress((void**)&part_exp, g_part_exp);
    cudaGetSymbolAddress((void**)&outflat,  g_outflat);
    cudaGetSymbolAddress((void**)&spk_moe,  g_spk_moe);
    cudaGetSymbolAddress((void**)&decoded,  g_decoded);

    const float* Xr    = rnd + RN_X;
    const float* encWr = rnd + RN_EW;
    const float* s2cWr = rnd + RN_SW;
    const float* We1r  = rnd + RN_W1;
    const float* We2r  = rnd + RN_W2;
    const float* c2sWr = rnd + RN_CW;
    const float* decWr = rnd + RN_DW;

    auto kEnc = fused_gemm2<false>;
    auto kExp = fused_gemm2<true>;
    auto kC2s = mma_gemm<1>;
    auto kDec = mma_gemm<0>;

    cudaFuncSetAttribute(kEnc, cudaFuncAttributeMaxDynamicSharedMemorySize, FUSED_SMEM);
    cudaFuncSetAttribute(kExp, cudaFuncAttributeMaxDynamicSharedMemorySize, FUSED_SMEM);
    cudaFuncSetAttribute(kC2s, cudaFuncAttributeMaxDynamicSharedMemorySize, PIPE2_SMEM);
    cudaFuncSetAttribute(kDec, cudaFuncAttributeMaxDynamicSharedMemorySize, PIPE2_SMEM);

    // 0) pre-round (X permuted), zero counts
    round_all<<<(RN_TOT / 4 + 255) / 256, 256>>>(X, enc_W, s2c_W, We1, We2, c2s_W, dec_W);

    // 1) fused encoder+s2c
    kEnc<<<dim3(S2C_SPLIT, NTOK / BM), 256, FUSED_SMEM>>>(
        Xr, encWr, enc_b, s2cWr, part_s2c, DDIM, DDIM, HDIM, nullptr, nullptr);

    // 2) routing (emits permuted cont)
    router_kernel<<<NTOK, 64>>>(part_s2c, s2c_b, cont, rW1, rb1, rW2, rb2, ae, aw);

    // 3) fused expert MLP
    kExp<<<dim3(EXP_SPLIT, ECAP / BM, EEXP), 256, FUSED_SMEM>>>(
        cont, We1r, be1, We2r, part_exp, MDIM, MDIM, HHALF, bucket, count);

    // 4) combine (emits permuted outflat)
    combine_kernel<<<(NTOK * MDIM) / 256, 256>>>(part_exp, ae, aw, be2, outflat);

    // 5) c2s -> tf32-rounded, k-permuted spk_moe
    kC2s<<<dim3(HDIM / BN, NTOK / BM), 256, PIPE2_SMEM>>>(
        outflat, c2sWr, c2s_b, spk_moe, MDIM, HDIM);

    // 6) decoder -> fp32 decoded
    kDec<<<dim3(DDIM / BN, NTOK / BM), 256, PIPE2_SMEM>>>(
        spk_moe, decWr, dec_b, decoded, HDIM, DDIM);

    // 7) layernorm -> d_out
    layernorm_kernel<<<NTOK, 256>>>(decoded, ln_g, ln_b, (float*)d_out);
}

// round 10
// speedup vs baseline: 1.5922x; 1.5922x over previous
#include <cuda_runtime.h>
#include <cuda_fp16.h>
#include <math.h>
#include <stdint.h>

#define NTOK 8192
#define DDIM 1024
#define HDIM 2048
#define MDIM 64
#define EEXP 8
#define HHALF 1024
#define ECAP 8192
#define NASSIGN (NTOK * 2)
#define S2C_SPLIT 16
#define EXP_SPLIT 8

// ---------------------------------------------------------------------------
// fp16 buffers: A-side natural half rows; B-side k-pair-packed half2 words
// ---------------------------------------------------------------------------
__device__ __half   g_Xh[(size_t)NTOK * DDIM];
__device__ uint32_t g_encWp[(size_t)(DDIM / 2) * HDIM];     // [512][2048]
__device__ uint32_t g_s2cWp[(size_t)(HDIM / 2) * MDIM];     // [1024][64]
__device__ uint32_t g_We1p[(size_t)EEXP * (MDIM / 2) * HHALF];
__device__ uint32_t g_We2p[(size_t)EEXP * (HHALF / 2) * MDIM];
__device__ uint32_t g_c2sWp[(size_t)(MDIM / 2) * HDIM];
__device__ uint32_t g_decWp[(size_t)(HDIM / 2) * DDIM];

__device__ float  g_part_s2c[(size_t)S2C_SPLIT * NTOK * MDIM];
__device__ __half g_cont[(size_t)NTOK * MDIM];
__device__ int    g_assign_e[NASSIGN];
__device__ float  g_assign_w[NASSIGN];
__device__ int    g_count[EEXP];
__device__ int    g_bucket[EEXP * ECAP];
__device__ float  g_part_exp[(size_t)EXP_SPLIT * NASSIGN * MDIM];
__device__ __half g_outflat[(size_t)NTOK * MDIM];
__device__ __half g_spk_moe[(size_t)NTOK * HDIM];
__device__ float  g_decoded[(size_t)NTOK * DDIM];

__device__ __forceinline__ float sigf(float x) { return 1.0f / (1.0f + expf(-x)); }
__device__ __forceinline__ void cp16(void* dst, const void* src) {
    unsigned d = (unsigned)__cvta_generic_to_shared(dst);
    asm volatile("cp.async.cg.shared.global [%0], [%1], 16;\n" :: "r"(d), "l"(src));
}
__device__ __forceinline__ void cp_commit() { asm volatile("cp.async.commit_group;\n"); }
template<int N> __device__ __forceinline__ void cp_wait() {
    asm volatile("cp.async.wait_group %0;\n" :: "n"(N));
}
__device__ __forceinline__ void mma_f16(float c[4], const uint32_t a[4], const uint32_t b[2]) {
    asm volatile(
        "mma.sync.aligned.m16n8k16.row.col.f32.f16.f16.f32 "
        "{%0,%1,%2,%3}, {%4,%5,%6,%7}, {%8,%9}, {%0,%1,%2,%3};\n"
        : "+f"(c[0]), "+f"(c[1]), "+f"(c[2]), "+f"(c[3])
        : "r"(a[0]), "r"(a[1]), "r"(a[2]), "r"(a[3]), "r"(b[0]), "r"(b[1]));
}
__device__ __forceinline__ uint32_t h2u(float a, float b) {
    __half2 h = __floats2half2_rn(a, b);
    return *(uint32_t*)&h;
}

// fused (enc/expert): BK16 halfs, 4 stages. A [m][kp-words] stride 12, B [kp][n] stride 136.
#define BM 128
#define BN 128
#define AS 12
#define BS1 136
#define STAGES 4
#define STG_W (BM * AS + 8 * BS1)          // 2624 words / stage
#define W2_OFF (STAGES * STG_W)            // 10496
#define W2_S 72
#define SPIKE_S 68
#define FUSED_SMEM ((W2_OFF + 64 * W2_S) * 4)   // 60416 B
// plain (c2s/dec): BK32 halfs, 3 stages. A stride 20 words, B 16 x 136.
#define AS2 20
#define BS2 136
#define ST2 3
#define PIPE2_SMEM (ST2 * (BM * AS2 + 16 * BS2) * 4)   // 56832 B

// ---------------------------------------------------------------------------
// Prep: X -> half (adjacent pack); weights -> k-pair-packed half2 words.
// All word offsets:
// ---------------------------------------------------------------------------
#define PK_X   0UL
#define PK_EW  4194304UL
#define PK_SW  5242880UL
#define PK_W1  5308416UL
#define PK_W2  5570560UL
#define PK_CW  5832704UL
#define PK_DW  5898240UL
#define PK_TOT 6946816UL

__global__ void prep_all(const float* __restrict__ X,   const float* __restrict__ encW,
                         const float* __restrict__ s2cW, const float* __restrict__ We1,
                         const float* __restrict__ We2,  const float* __restrict__ c2sW,
                         const float* __restrict__ decW)
{
    if (blockIdx.x == 0 && threadIdx.x < EEXP) g_count[threadIdx.x] = 0;
    const size_t f = (size_t)blockIdx.x * 256 + threadIdx.x;
    if (f >= PK_TOT) return;
    if (f < PK_EW) {
        float2 v = *(const float2*)&X[2 * f];
        ((__half2*)g_Xh)[f] = __floats2half2_rn(v.x, v.y);
        return;
    }
    const float* src; uint32_t* dst; size_t local; int N;
    if      (f < PK_SW) { src = encW; dst = g_encWp; local = f - PK_EW; N = HDIM; }
    else if (f < PK_W1) { src = s2cW; dst = g_s2cWp; local = f - PK_SW; N = MDIM; }
    else if (f < PK_W2) { src = We1;  dst = g_We1p;  local = f - PK_W1; N = HHALF; }
    else if (f < PK_CW) { src = We2;  dst = g_We2p;  local = f - PK_W2; N = MDIM; }
    else if (f < PK_DW) { src = c2sW; dst = g_c2sWp; local = f - PK_CW; N = HDIM; }
    else                { src = decW; dst = g_decWp; local = f - PK_DW; N = DDIM; }
    const size_t kp = local / N, n = local % N;
    const float w0 = src[(2 * kp) * (size_t)N + n];
    const float w1 = src[(2 * kp + 1) * (size_t)N + n];
    ((__half2*)dst)[local] = __floats2half2_rn(w0, w1);
}

// ---------------------------------------------------------------------------
// Fused GEMM+GEMM, fp16 operands.
//   EXPM=false: enc+s2c.   EXPM=true: expert MLP (gather/scatter).
// ---------------------------------------------------------------------------
template<bool EXPM>
__global__ __launch_bounds__(256, 2)
void fused_gemm2(const __half* __restrict__ A, const uint32_t* __restrict__ W1p,
                 const float* __restrict__ b1, const uint32_t* __restrict__ W2p,
                 float* __restrict__ Cpart, int K, int lda, int ldw1,
                 const int* __restrict__ bucket, const int* __restrict__ count)
{
    extern __shared__ uint32_t smw[];
    uint32_t* spike = smw;               // [128][SPIKE_S] words (aliases pipeline)
    uint32_t* w2s   = smw + W2_OFF;      // [64][W2_S] words

    const int tid = threadIdx.x, lane = tid & 31, w = tid >> 5;
    const int g = lane >> 2, tg = lane & 3;
    const int wm = w >> 2, wn = w & 3;
    const int bm0 = blockIdx.y * BM, bn0 = blockIdx.x * BN;
    const int e = EXPM ? blockIdx.z : 0;

    int cnt = 0;
    if (EXPM) {
        cnt = count[e];
        if (bm0 >= cnt) return;
    }

    const uint32_t* W1 = EXPM ? W1p + (size_t)e * (MDIM / 2) * HHALF : W1p;
    const float*    bb = EXPM ? b1 + (size_t)e * HHALF : b1;
    const uint32_t* W2 = EXPM ? W2p + (size_t)e * (HHALF / 2) * MDIM : W2p;

    // Per-thread A row (1 cp16 per K-tile per thread: row = tid>>1, chunk = tid&1)
    const int arow = bm0 + (tid >> 1);
    size_t aoff;
    if (EXPM) {
        const int rr = (arow < cnt) ? arow : (cnt - 1);
        aoff = (size_t)(bucket[e * ECAP + rr] >> 1) * MDIM;
    } else {
        aoff = (size_t)arow * lda;
    }
    const int achunk = (tid & 1);

    // Prefetch W2 chunk (64 packed rows x 64 words), oldest cp.async group
#pragma unroll
    for (int it = 0; it < 4; it++) {
        int idx = tid + it * 256;
        int r = idx >> 4, c = idx & 15;
        cp16(&w2s[r * W2_S + c * 4], &W2[(size_t)(bn0 / 2 + r) * MDIM + c * 4]);
    }
    cp_commit();

    float c[4][4][4];
#pragma unroll
    for (int i = 0; i < 4; i++)
#pragma unroll
        for (int j = 0; j < 4; j++)
#pragma unroll
            for (int q = 0; q < 4; q++) c[i][j][q] = 0.0f;

    const int nk = K / 16;
    auto issue = [&](int st, int kt) {
        const int k0 = kt * 16;                       // halfs
        uint32_t* as = smw + st * STG_W;
        uint32_t* bs = as + BM * AS;
        cp16(&as[(tid >> 1) * AS + achunk * 4], A + aoff + k0 + achunk * 8);
        {
            int r = tid >> 5, cc = tid & 31;
            cp16(&bs[r * BS1 + cc * 4],
                 &W1[(size_t)(kt * 8 + r) * ldw1 + bn0 + cc * 4]);
        }
    };

#pragma unroll
    for (int s = 0; s < STAGES - 1; s++) {
        if (s < nk) issue(s, s);
        cp_commit();
    }
    for (int kt = 0; kt < nk; kt++) {
        cp_wait<STAGES - 2>();
        __syncthreads();
        const int st = kt % STAGES;
        const uint32_t* as = smw + st * STG_W;
        const uint32_t* bs = as + BM * AS;
        uint32_t a[4][4], b[4][2];
#pragma unroll
        for (int mf = 0; mf < 4; mf++) {
            const int m0 = wm * 64 + mf * 16;
            a[mf][0] = as[(m0 + g)     * AS + tg];
            a[mf][1] = as[(m0 + g + 8) * AS + tg];
            a[mf][2] = as[(m0 + g)     * AS + tg + 4];
            a[mf][3] = as[(m0 + g + 8) * AS + tg + 4];
        }
#pragma unroll
        for (int nf = 0; nf < 4; nf++) {
            const int n0 = wn * 32 + nf * 8 + g;
            b[nf][0] = bs[tg * BS1 + n0];
            b[nf][1] = bs[(tg + 4) * BS1 + n0];
        }
#pragma unroll
        for (int mf = 0; mf < 4; mf++)
#pragma unroll
            for (int nf = 0; nf < 4; nf++) mma_f16(c[mf][nf], a[mf], b[nf]);
        const int nxt = kt + STAGES - 1;
        if (nxt < nk) issue(nxt % STAGES, nxt);
        cp_commit();
    }

    cp_wait<0>();
    __syncthreads();
    // Activated tile -> smem spike as half2 words
#pragma unroll
    for (int mf = 0; mf < 4; mf++)
#pragma unroll
        for (int nf = 0; nf < 4; nf++) {
            const int col = wn * 32 + nf * 8 + 2 * tg;
            const int r0  = wm * 64 + mf * 16 + g;
#pragma unroll
            for (int h = 0; h < 2; h++) {
                const int row = r0 + h * 8;
                float v0 = c[mf][nf][h * 2 + 0] + bb[bn0 + col];
                float v1 = c[mf][nf][h * 2 + 1] + bb[bn0 + col + 1];
                if (EXPM) { v0 = fmaxf(v0, 0.0f); v1 = fmaxf(v1, 0.0f); }
                else      { v0 = sigf(v0);        v1 = sigf(v1); }
                spike[row * SPIKE_S + (col >> 1)] = h2u(v0, v1);
            }
        }
    __syncthreads();

    // mini GEMM: part[128x64] = spike(128x128 halfs) @ w2s
    const int wm2 = w >> 1, wn2 = w & 1;
    float c2[2][4][4];
#pragma unroll
    for (int i = 0; i < 2; i++)
#pragma unroll
        for (int j = 0; j < 4; j++)
#pragma unroll
            for (int q = 0; q < 4; q++) c2[i][j][q] = 0.0f;
#pragma unroll
    for (int s = 0; s < 8; s++) {          // K=128 halfs = 8 k16 steps
        uint32_t a[2][4], b[4][2];
#pragma unroll
        for (int mf = 0; mf < 2; mf++) {
            const int m0 = wm2 * 32 + mf * 16;
            a[mf][0] = spike[(m0 + g)     * SPIKE_S + s * 8 + tg];
            a[mf][1] = spike[(m0 + g + 8) * SPIKE_S + s * 8 + tg];
            a[mf][2] = spike[(m0 + g)     * SPIKE_S + s * 8 + tg + 4];
            a[mf][3] = spike[(m0 + g + 8) * SPIKE_S + s * 8 + tg + 4];
        }
#pragma unroll
        for (int nf = 0; nf < 4; nf++) {
            const int n0 = wn2 * 32 + nf * 8 + g;
            b[nf][0] = w2s[(s * 8 + tg)     * W2_S + n0];
            b[nf][1] = w2s[(s * 8 + tg + 4) * W2_S + n0];
        }
#pragma unroll
        for (int mf = 0; mf < 2; mf++)
#pragma unroll
            for (int nf = 0; nf < 4; nf++) mma_f16(c2[mf][nf], a[mf], b[nf]);
    }
    const size_t sb = (size_t)blockIdx.x * (EXPM ? NASSIGN : NTOK) * MDIM;
#pragma unroll
    for (int mf = 0; mf < 2; mf++)
#pragma unroll
        for (int nf = 0; nf < 4; nf++) {
            const int col = wn2 * 32 + nf * 8 + 2 * tg;
            const int r0  = wm2 * 32 + mf * 16 + g;
#pragma unroll
            for (int h = 0; h < 2; h++) {
                const int row = r0 + h * 8;
                if (EXPM) {
                    if (bm0 + row < cnt) {
                        const int i = bucket[e * ECAP + bm0 + row];
                        *(float2*)&Cpart[sb + (size_t)i * MDIM + col] =
                            make_float2(c2[mf][nf][h * 2 + 0], c2[mf][nf][h * 2 + 1]);
                    }
                } else {
                    *(float2*)&Cpart[sb + (size_t)(bm0 + row) * MDIM + col] =
                        make_float2(c2[mf][nf][h * 2 + 0], c2[mf][nf][h * 2 + 1]);
                }
            }
        }
}

// ---------------------------------------------------------------------------
// Plain GEMM BK32 halfs, 3 stages. MODE 0: dec (fp32 out). MODE 1: c2s (half out).
// ---------------------------------------------------------------------------
template<int MODE>
__global__ __launch_bounds__(256, 2)
void mma_gemm(const __half* __restrict__ A, const uint32_t* __restrict__ Wp,
              const float* __restrict__ bias, void* __restrict__ Cv,
              int K, int Hout)
{
    extern __shared__ uint32_t smw[];
    const int tid = threadIdx.x, lane = tid & 31, w = tid >> 5;
    const int g = lane >> 2, tg = lane & 3;
    const int wm = w >> 2, wn = w & 3;
    const int bm0 = blockIdx.y * BM, bn0 = blockIdx.x * BN;

    float c[4][4][4];
#pragma unroll
    for (int i = 0; i < 4; i++)
#pragma unroll
        for (int j = 0; j < 4; j++)
#pragma unroll
            for (int q = 0; q < 4; q++) c[i][j][q] = 0.0f;

    const int nk = K / 32;
    auto issue = [&](int st, int kt) {
        const int k0 = kt * 32;
        uint32_t* as = smw + st * (BM * AS2 + 16 * BS2);
        uint32_t* bs = as + BM * AS2;
#pragma unroll
        for (int it = 0; it < 2; it++) {
            int idx = tid + it * 256;
            int r = idx >> 2, c4 = idx & 3;
            cp16(&as[r * AS2 + c4 * 4], A + (size_t)(bm0 + r) * K + k0 + c4 * 8);
        }
#pragma unroll
        for (int it = 0; it < 2; it++) {
            int idx = tid + it * 256;
            int r = idx >> 5, cc = idx & 31;
            cp16(&bs[r * BS2 + cc * 4],
                 &Wp[(size_t)(kt * 16 + r) * Hout + bn0 + cc * 4]);
        }
    };

#pragma unroll
    for (int s = 0; s < ST2 - 1; s++) {
        if (s < nk) issue(s, s);
        cp_commit();
    }
    for (int kt = 0; kt < nk; kt++) {
        cp_wait<ST2 - 2>();
        __syncthreads();
        const int st = kt % ST2;
        const uint32_t* as = smw + st * (BM * AS2 + 16 * BS2);
        const uint32_t* bs = as + BM * AS2;
#pragma unroll
        for (int ks = 0; ks < 2; ks++) {
            uint32_t a[4][4], b[4][2];
#pragma unroll
            for (int mf = 0; mf < 4; mf++) {
                const int m0 = wm * 64 + mf * 16;
                a[mf][0] = as[(m0 + g)     * AS2 + ks * 8 + tg];
                a[mf][1] = as[(m0 + g + 8) * AS2 + ks * 8 + tg];
                a[mf][2] = as[(m0 + g)     * AS2 + ks * 8 + tg + 4];
                a[mf][3] = as[(m0 + g + 8) * AS2 + ks * 8 + tg + 4];
            }
#pragma unroll
            for (int nf = 0; nf < 4; nf++) {
                const int n0 = wn * 32 + nf * 8 + g;
                b[nf][0] = bs[(ks * 8 + tg)     * BS2 + n0];
                b[nf][1] = bs[(ks * 8 + tg + 4) * BS2 + n0];
            }
#pragma unroll
            for (int mf = 0; mf < 4; mf++)
#pragma unroll
                for (int nf = 0; nf < 4; nf++) mma_f16(c[mf][nf], a[mf], b[nf]);
        }
        const int nxt = kt + ST2 - 1;
        if (nxt < nk) issue(nxt % ST2, nxt);
        cp_commit();
    }

#pragma unroll
    for (int mf = 0; mf < 4; mf++)
#pragma unroll
        for (int nf = 0; nf < 4; nf++) {
            const int col = bn0 + wn * 32 + nf * 8 + 2 * tg;
            const int r0  = bm0 + wm * 64 + mf * 16 + g;
#pragma unroll
            for (int h = 0; h < 2; h++) {
                const int row = r0 + h * 8;
                float v0 = sigf(c[mf][nf][h * 2 + 0] + bias[col]);
                float v1 = sigf(c[mf][nf][h * 2 + 1] + bias[col + 1]);
                if (MODE == 1) {
                    ((uint32_t*)Cv)[(size_t)row * (Hout / 2) + (col >> 1)] = h2u(v0, v1);
                } else {
                    *(float2*)&((float*)Cv)[(size_t)row * Hout + col] = make_float2(v0, v1);
                }
            }
        }
}

// ---------------------------------------------------------------------------
__global__ void router_kernel(const float* __restrict__ part_s2c,
                              const float* __restrict__ s2c_b,
                              __half* __restrict__ cont,
                              const float* __restrict__ rW1, const float* __restrict__ rb1,
                              const float* __restrict__ rW2, const float* __restrict__ rb2,
                              int* __restrict__ assign_e, float* __restrict__ assign_w)
{
    __shared__ float cs[64], hid[64], logit[8];
    const int n = blockIdx.x, t = threadIdx.x;

    float cv = s2c_b[t];
#pragma unroll
    for (int s = 0; s < S2C_SPLIT; s++)
        cv += part_s2c[(size_t)s * NTOK * MDIM + (size_t)n * MDIM + t];
    cont[(size_t)n * MDIM + t] = __float2half_rn(cv);
    cs[t] = cv;
    __syncthreads();

    float a = rb1[t];
#pragma unroll
    for (int m = 0; m < 64; m++) a = fmaf(cs[m], rW1[m * 64 + t], a);
    hid[t] = tanhf(a);
    __syncthreads();

    if (t < EEXP) {
        float l = rb2[t];
#pragma unroll
        for (int j = 0; j < 64; j++) l = fmaf(hid[j], rW2[j * EEXP + t], l);
        logit[t] = l;
    }
    __syncthreads();

    if (t == 0) {
        float mx = logit[0];
        for (int e = 1; e < EEXP; e++) mx = fmaxf(mx, logit[e]);
        float p[EEXP];
        for (int e = 0; e < EEXP; e++) p[e] = expf(logit[e] - mx);
        int i1 = 0;
        for (int e = 1; e < EEXP; e++) if (p[e] > p[i1]) i1 = e;
        int i2 = (i1 == 0) ? 1 : 0;
        for (int e = 0; e < EEXP; e++) if (e != i1 && p[e] > p[i2]) i2 = e;
        const float denom = p[i1] + p[i2];
        const int ids[2] = {i1, i2};
        const float ws[2] = {p[i1] / denom, p[i2] / denom};
#pragma unroll
        for (int k = 0; k < 2; k++) {
            const int i = n * 2 + k;
            assign_e[i] = ids[k];
            assign_w[i] = ws[k];
            const int slot = atomicAdd(&g_count[ids[k]], 1);
            g_bucket[ids[k] * ECAP + slot] = i;
        }
    }
}

__global__ void combine_kernel(const float* __restrict__ part_exp,
                               const int* __restrict__ ae, const float* __restrict__ aw,
                               const float* __restrict__ be2, __half* __restrict__ outflat)
{
    const int i = blockIdx.x * 256 + threadIdx.x;
    const int n = i >> 6, m = i & 63;
    float acc = 0.0f;
#pragma unroll
    for (int k = 0; k < 2; k++) {
        const int idx = 2 * n + k;
        float s = be2[ae[idx] * MDIM + m];
#pragma unroll
        for (int sp = 0; sp < EXP_SPLIT; sp++)
            s += part_exp[(size_t)sp * NASSIGN * MDIM + (size_t)idx * MDIM + m];
        acc = fmaf(aw[idx], s, acc);
    }
    outflat[i] = __float2half_rn(acc);
}

__global__ void layernorm_kernel(const float* __restrict__ x,
                                 const float* __restrict__ g, const float* __restrict__ b,
                                 float* __restrict__ out)
{
    const int n = blockIdx.x, t = threadIdx.x;
    const float* row = x + (size_t)n * DDIM;
    float v[4];
    float s = 0.0f, s2 = 0.0f;
#pragma unroll
    for (int i = 0; i < 4; i++) {
        v[i] = row[t + i * 256];
        s += v[i]; s2 += v[i] * v[i];
    }
#pragma unroll
    for (int o = 16; o > 0; o >>= 1) {
        s  += __shfl_xor_sync(0xFFFFFFFFu, s, o);
        s2 += __shfl_xor_sync(0xFFFFFFFFu, s2, o);
    }
    __shared__ float sh1[8], sh2[8], mu_s, rstd_s;
    const int warp = t >> 5, lane = t & 31;
    if (lane == 0) { sh1[warp] = s; sh2[warp] = s2; }
    __syncthreads();
    if (t == 0) {
        float S = 0.0f, S2 = 0.0f;
        for (int wq = 0; wq < 8; wq++) { S += sh1[wq]; S2 += sh2[wq]; }
        float mu = S / (float)DDIM;
        mu_s = mu;
        rstd_s = rsqrtf(S2 / (float)DDIM - mu * mu + 1e-5f);
    }
    __syncthreads();
    const float mu = mu_s, rstd = rstd_s;
    float* orow = out + (size_t)n * DDIM;
#pragma unroll
    for (int i = 0; i < 4; i++) {
        int col = t + i * 256;
        orow[col] = (v[i] - mu) * rstd * g[col] + b[col];
    }
}

// ---------------------------------------------------------------------------
extern "C" void kernel_launch(void* const* d_in, const int* in_sizes, int n_in,
                              void* d_out, int out_size)
{
    const float* X     = (const float*)d_in[0];
    const float* enc_W = (const float*)d_in[1];
    const float* enc_b = (const float*)d_in[2];
    const float* s2c_W = (const float*)d_in[3];
    const float* s2c_b = (const float*)d_in[4];
    const float* rW1   = (const float*)d_in[5];
    const float* rb1   = (const float*)d_in[6];
    const float* rW2   = (const float*)d_in[7];
    const float* rb2   = (const float*)d_in[8];
    const float* We1   = (const float*)d_in[9];
    const float* be1   = (const float*)d_in[10];
    const float* We2   = (const float*)d_in[11];
    const float* be2   = (const float*)d_in[12];
    const float* c2s_W = (const float*)d_in[13];
    const float* c2s_b = (const float*)d_in[14];
    const float* dec_W = (const float*)d_in[15];
    const float* dec_b = (const float*)d_in[16];
    const float* ln_g  = (const float*)d_in[17];
    const float* ln_b  = (const float*)d_in[18];

    __half *Xh, *cont, *outflat, *spk_moe;
    uint32_t *encWp, *s2cWp, *We1p, *We2p, *c2sWp, *decWp;
    float *part_s2c, *aw, *part_exp, *decoded;
    int *ae, *bucket, *count;
    cudaGetSymbolAddress((void**)&Xh,       g_Xh);
    cudaGetSymbolAddress((void**)&encWp,    g_encWp);
    cudaGetSymbolAddress((void**)&s2cWp,    g_s2cWp);
    cudaGetSymbolAddress((void**)&We1p,     g_We1p);
    cudaGetSymbolAddress((void**)&We2p,     g_We2p);
    cudaGetSymbolAddress((void**)&c2sWp,    g_c2sWp);
    cudaGetSymbolAddress((void**)&decWp,    g_decWp);
    cudaGetSymbolAddress((void**)&part_s2c, g_part_s2c);
    cudaGetSymbolAddress((void**)&cont,     g_cont);
    cudaGetSymbolAddress((void**)&ae,       g_assign_e);
    cudaGetSymbolAddress((void**)&aw,       g_assign_w);
    cudaGetSymbolAddress((void**)&count,    g_count);
    cudaGetSymbolAddress((void**)&bucket,   g_bucket);
    cudaGetSymbolAddress((void**)&part_exp, g_part_exp);
    cudaGetSymbolAddress((void**)&outflat,  g_outflat);
    cudaGetSymbolAddress((void**)&spk_moe,  g_spk_moe);
    cudaGetSymbolAddress((void**)&decoded,  g_decoded);

    auto kEnc = fused_gemm2<false>;
    auto kExp = fused_gemm2<true>;
    auto kC2s = mma_gemm<1>;
    auto kDec = mma_gemm<0>;
    cudaFuncSetAttribute(kEnc, cudaFuncAttributeMaxDynamicSharedMemorySize, FUSED_SMEM);
    cudaFuncSetAttribute(kExp, cudaFuncAttributeMaxDynamicSharedMemorySize, FUSED_SMEM);
    cudaFuncSetAttribute(kC2s, cudaFuncAttributeMaxDynamicSharedMemorySize, PIPE2_SMEM);
    cudaFuncSetAttribute(kDec, cudaFuncAttributeMaxDynamicSharedMemorySize, PIPE2_SMEM);

    // 0) prep: fp16 conversion + k-pair packing + zero counts
    prep_all<<<(PK_TOT + 255) / 256, 256>>>(X, enc_W, s2c_W, We1, We2, c2s_W, dec_W);

    // 1) fused encoder+s2c (K=1024 halfs)
    kEnc<<<dim3(S2C_SPLIT, NTOK / BM), 256, FUSED_SMEM>>>(
        Xh, encWp, enc_b, s2cWp, part_s2c, DDIM, DDIM, HDIM, nullptr, nullptr);

    // 2) routing
    router_kernel<<<NTOK, 64>>>(part_s2c, s2c_b, cont, rW1, rb1, rW2, rb2, ae, aw);

    // 3) fused expert MLP (K=64 halfs)
    kExp<<<dim3(EXP_SPLIT, ECAP / BM, EEXP), 256, FUSED_SMEM>>>(
        cont, We1p, be1, We2p, part_exp, MDIM, MDIM, HHALF, bucket, count);

    // 4) combine
    combine_kernel<<<(NTOK * MDIM) / 256, 256>>>(part_exp, ae, aw, be2, outflat);

    // 5) c2s: sigmoid -> half spk_moe (K=64)
    kC2s<<<dim3(HDIM / BN, NTOK / BM), 256, PIPE2_SMEM>>>(
        outflat, c2sWp, c2s_b, spk_moe, MDIM, HDIM);

    // 6) decoder: sigmoid -> fp32 decoded (K=2048)
    kDec<<<dim3(DDIM / BN, NTOK / BM), 256, PIPE2_SMEM>>>(
        spk_moe, decWp, dec_b, decoded, HDIM, DDIM);

    // 7) layernorm -> d_out
    layernorm_kernel<<<NTOK, 256>>>(decoded, ln_g, ln_b, (float*)d_out);
}

// round 11
// speedup vs baseline: 1.6602x; 1.0427x over previous
#include <cuda_runtime.h>
#include <cuda_fp16.h>
#include <math.h>
#include <stdint.h>

#define NTOK 8192
#define DDIM 1024
#define HDIM 2048
#define MDIM 64
#define EEXP 8
#define HHALF 1024
#define ECAP 8192
#define NASSIGN (NTOK * 2)
#define S2C_SPLIT 16
#define EXP_SPLIT 8

// ---------------------------------------------------------------------------
// fp16 buffers: A-side natural half rows; B-side k-pair-packed half2 words
// ---------------------------------------------------------------------------
__device__ __half   g_Xh[(size_t)NTOK * DDIM];
__device__ uint32_t g_encWp[(size_t)(DDIM / 2) * HDIM];
__device__ uint32_t g_s2cWp[(size_t)(HDIM / 2) * MDIM];
__device__ uint32_t g_We1p[(size_t)EEXP * (MDIM / 2) * HHALF];
__device__ uint32_t g_We2p[(size_t)EEXP * (HHALF / 2) * MDIM];
__device__ uint32_t g_c2sWp[(size_t)(MDIM / 2) * HDIM];
__device__ uint32_t g_decWp[(size_t)(HDIM / 2) * DDIM];

__device__ float  g_part_s2c[(size_t)S2C_SPLIT * NTOK * MDIM];
__device__ __half g_cont[(size_t)NTOK * MDIM];
__device__ int    g_assign_e[NASSIGN];
__device__ float  g_assign_w[NASSIGN];
__device__ int    g_count[EEXP];
__device__ int    g_bucket[EEXP * ECAP];
__device__ float  g_part_exp[(size_t)EXP_SPLIT * NASSIGN * MDIM];
__device__ __half g_outflat[(size_t)NTOK * MDIM];
__device__ __half g_spk_moe[(size_t)NTOK * HDIM];
__device__ float  g_decoded[(size_t)NTOK * DDIM];

__device__ __forceinline__ float sigf(float x) { return 1.0f / (1.0f + expf(-x)); }
__device__ __forceinline__ void cp16(void* dst, const void* src) {
    unsigned d = (unsigned)__cvta_generic_to_shared(dst);
    asm volatile("cp.async.cg.shared.global [%0], [%1], 16;\n" :: "r"(d), "l"(src));
}
__device__ __forceinline__ void cp_commit() { asm volatile("cp.async.commit_group;\n"); }
template<int N> __device__ __forceinline__ void cp_wait() {
    asm volatile("cp.async.wait_group %0;\n" :: "n"(N));
}
__device__ __forceinline__ void mma_f16(float c[4], const uint32_t a[4], const uint32_t b[2]) {
    asm volatile(
        "mma.sync.aligned.m16n8k16.row.col.f32.f16.f16.f32 "
        "{%0,%1,%2,%3}, {%4,%5,%6,%7}, {%8,%9}, {%0,%1,%2,%3};\n"
        : "+f"(c[0]), "+f"(c[1]), "+f"(c[2]), "+f"(c[3])
        : "r"(a[0]), "r"(a[1]), "r"(a[2]), "r"(a[3]), "r"(b[0]), "r"(b[1]));
}
__device__ __forceinline__ uint32_t h2u(float a, float b) {
    __half2 h = __floats2half2_rn(a, b);
    return *(uint32_t*)&h;
}

// fused (enc/expert): BK=32 halfs (16 kp-words), 4 stages.
// A [m][kp] stride 20 words, B [kp][n] stride 136 words.
#define BM 128
#define BN 128
#define AS 20
#define BS1 136
#define STAGES 4
#define STG_W (BM * AS + 16 * BS1)          // 4736 words / stage
#define W2_OFF (STAGES * STG_W)             // 18944
#define W2_S 72
#define SPIKE_S 68
#define FUSED_SMEM ((W2_OFF + 64 * W2_S) * 4)   // 94208 B

// plain (c2s/dec): BK=64 halfs (32 kp-words), 3 stages. A stride 36, B 32 x 136.
#define AS2 36
#define BS2 136
#define ST2 3
#define STG2_W (BM * AS2 + 32 * BS2)        // 8960 words / stage
#define PIPE2_SMEM (ST2 * STG2_W * 4)       // 107520 B

// ---------------------------------------------------------------------------
// Prep: X -> half; weights -> k-pair-packed half2 words. Word offsets:
// ---------------------------------------------------------------------------
#define PK_X   0UL
#define PK_EW  4194304UL
#define PK_SW  5242880UL
#define PK_W1  5308416UL
#define PK_W2  5570560UL
#define PK_CW  5832704UL
#define PK_DW  5898240UL
#define PK_TOT 6946816UL

__global__ void prep_all(const float* __restrict__ X,   const float* __restrict__ encW,
                         const float* __restrict__ s2cW, const float* __restrict__ We1,
                         const float* __restrict__ We2,  const float* __restrict__ c2sW,
                         const float* __restrict__ decW)
{
    if (blockIdx.x == 0 && threadIdx.x < EEXP) g_count[threadIdx.x] = 0;
    const size_t f = (size_t)blockIdx.x * 256 + threadIdx.x;
    if (f >= PK_TOT) return;
    if (f < PK_EW) {
        float2 v = *(const float2*)&X[2 * f];
        ((__half2*)g_Xh)[f] = __floats2half2_rn(v.x, v.y);
        return;
    }
    const float* src; uint32_t* dst; size_t local; int N;
    if      (f < PK_SW) { src = encW; dst = g_encWp; local = f - PK_EW; N = HDIM; }
    else if (f < PK_W1) { src = s2cW; dst = g_s2cWp; local = f - PK_SW; N = MDIM; }
    else if (f < PK_W2) { src = We1;  dst = g_We1p;  local = f - PK_W1; N = HHALF; }
    else if (f < PK_CW) { src = We2;  dst = g_We2p;  local = f - PK_W2; N = MDIM; }
    else if (f < PK_DW) { src = c2sW; dst = g_c2sWp; local = f - PK_CW; N = HDIM; }
    else                { src = decW; dst = g_decWp; local = f - PK_DW; N = DDIM; }
    const size_t kp = local / N, n = local % N;
    const float w0 = src[(2 * kp) * (size_t)N + n];
    const float w1 = src[(2 * kp + 1) * (size_t)N + n];
    ((__half2*)dst)[local] = __floats2half2_rn(w0, w1);
}

// ---------------------------------------------------------------------------
// Fused GEMM+GEMM, fp16, BK=32 halfs.
//   EXPM=false: enc+s2c.   EXPM=true: expert MLP (gather/scatter).
// ---------------------------------------------------------------------------
template<bool EXPM>
__global__ __launch_bounds__(256, 2)
void fused_gemm2(const __half* __restrict__ A, const uint32_t* __restrict__ W1p,
                 const float* __restrict__ b1, const uint32_t* __restrict__ W2p,
                 float* __restrict__ Cpart, int K, int lda, int ldw1,
                 const int* __restrict__ bucket, const int* __restrict__ count)
{
    extern __shared__ uint32_t smw[];
    uint32_t* spike = smw;               // [128][SPIKE_S] (aliases dead pipeline)
    uint32_t* w2s   = smw + W2_OFF;      // [64][W2_S]

    const int tid = threadIdx.x, lane = tid & 31, w = tid >> 5;
    const int g = lane >> 2, tg = lane & 3;
    const int wm = w >> 2, wn = w & 3;
    const int bm0 = blockIdx.y * BM, bn0 = blockIdx.x * BN;
    const int e = EXPM ? blockIdx.z : 0;

    int cnt = 0;
    if (EXPM) {
        cnt = count[e];
        if (bm0 >= cnt) return;
    }

    const uint32_t* W1 = EXPM ? W1p + (size_t)e * (MDIM / 2) * HHALF : W1p;
    const float*    bb = EXPM ? b1 + (size_t)e * HHALF : b1;
    const uint32_t* W2 = EXPM ? W2p + (size_t)e * (HHALF / 2) * MDIM : W2p;

    // A tile: 128 rows x 16 words = 512 cp16 -> 2/thread
    size_t aoff[2];
#pragma unroll
    for (int it = 0; it < 2; it++) {
        const int r = (tid + it * 256) >> 2;
        const int grow = bm0 + r;
        if (EXPM) {
            const int rr = (grow < cnt) ? grow : (cnt - 1);
            aoff[it] = (size_t)(bucket[e * ECAP + rr] >> 1) * MDIM;
        } else {
            aoff[it] = (size_t)grow * lda;
        }
    }

    // Prefetch W2 chunk (64 packed rows x 64 words), oldest group
#pragma unroll
    for (int it = 0; it < 4; it++) {
        int idx = tid + it * 256;
        int r = idx >> 4, c = idx & 15;
        cp16(&w2s[r * W2_S + c * 4], &W2[(size_t)(bn0 / 2 + r) * MDIM + c * 4]);
    }
    cp_commit();

    float c[4][4][4];
#pragma unroll
    for (int i = 0; i < 4; i++)
#pragma unroll
        for (int j = 0; j < 4; j++)
#pragma unroll
            for (int q = 0; q < 4; q++) c[i][j][q] = 0.0f;

    const int nk = K / 32;
    auto issue = [&](int st, int kt) {
        const int k0 = kt * 32;                       // halfs
        uint32_t* as = smw + st * STG_W;
        uint32_t* bs = as + BM * AS;
#pragma unroll
        for (int it = 0; it < 2; it++) {
            int idx = tid + it * 256;
            int r = idx >> 2, c4 = idx & 3;
            cp16(&as[r * AS + c4 * 4], A + aoff[it] + k0 + c4 * 8);
        }
#pragma unroll
        for (int it = 0; it < 2; it++) {
            int idx = tid + it * 256;
            int r = idx >> 5, cc = idx & 31;
            cp16(&bs[r * BS1 + cc * 4],
                 &W1[(size_t)(kt * 16 + r) * ldw1 + bn0 + cc * 4]);
        }
    };

#pragma unroll
    for (int s = 0; s < STAGES - 1; s++) {
        if (s < nk) issue(s, s);
        cp_commit();
    }
    for (int kt = 0; kt < nk; kt++) {
        cp_wait<STAGES - 2>();
        __syncthreads();
        const int st = kt % STAGES;
        const uint32_t* as = smw + st * STG_W;
        const uint32_t* bs = as + BM * AS;
#pragma unroll
        for (int ks = 0; ks < 2; ks++) {
            uint32_t a[4][4], b[4][2];
#pragma unroll
            for (int mf = 0; mf < 4; mf++) {
                const int m0 = wm * 64 + mf * 16;
                a[mf][0] = as[(m0 + g)     * AS + ks * 8 + tg];
                a[mf][1] = as[(m0 + g + 8) * AS + ks * 8 + tg];
                a[mf][2] = as[(m0 + g)     * AS + ks * 8 + tg + 4];
                a[mf][3] = as[(m0 + g + 8) * AS + ks * 8 + tg + 4];
            }
#pragma unroll
            for (int nf = 0; nf < 4; nf++) {
                const int n0 = wn * 32 + nf * 8 + g;
                b[nf][0] = bs[(ks * 8 + tg)     * BS1 + n0];
                b[nf][1] = bs[(ks * 8 + tg + 4) * BS1 + n0];
            }
#pragma unroll
            for (int mf = 0; mf < 4; mf++)
#pragma unroll
                for (int nf = 0; nf < 4; nf++) mma_f16(c[mf][nf], a[mf], b[nf]);
        }
        const int nxt = kt + STAGES - 1;
        if (nxt < nk) issue(nxt % STAGES, nxt);
        cp_commit();
    }

    cp_wait<0>();
    __syncthreads();
    // Activated tile -> smem spike as half2 words
#pragma unroll
    for (int mf = 0; mf < 4; mf++)
#pragma unroll
        for (int nf = 0; nf < 4; nf++) {
            const int col = wn * 32 + nf * 8 + 2 * tg;
            const int r0  = wm * 64 + mf * 16 + g;
#pragma unroll
            for (int h = 0; h < 2; h++) {
                const int row = r0 + h * 8;
                float v0 = c[mf][nf][h * 2 + 0] + bb[bn0 + col];
                float v1 = c[mf][nf][h * 2 + 1] + bb[bn0 + col + 1];
                if (EXPM) { v0 = fmaxf(v0, 0.0f); v1 = fmaxf(v1, 0.0f); }
                else      { v0 = sigf(v0);        v1 = sigf(v1); }
                spike[row * SPIKE_S + (col >> 1)] = h2u(v0, v1);
            }
        }
    __syncthreads();

    // mini GEMM: part[128x64] = spike(128x128 halfs) @ w2s
    const int wm2 = w >> 1, wn2 = w & 1;
    float c2[2][4][4];
#pragma unroll
    for (int i = 0; i < 2; i++)
#pragma unroll
        for (int j = 0; j < 4; j++)
#pragma unroll
            for (int q = 0; q < 4; q++) c2[i][j][q] = 0.0f;
#pragma unroll
    for (int s = 0; s < 8; s++) {
        uint32_t a[2][4], b[4][2];
#pragma unroll
        for (int mf = 0; mf < 2; mf++) {
            const int m0 = wm2 * 32 + mf * 16;
            a[mf][0] = spike[(m0 + g)     * SPIKE_S + s * 8 + tg];
            a[mf][1] = spike[(m0 + g + 8) * SPIKE_S + s * 8 + tg];
            a[mf][2] = spike[(m0 + g)     * SPIKE_S + s * 8 + tg + 4];
            a[mf][3] = spike[(m0 + g + 8) * SPIKE_S + s * 8 + tg + 4];
        }
#pragma unroll
        for (int nf = 0; nf < 4; nf++) {
            const int n0 = wn2 * 32 + nf * 8 + g;
            b[nf][0] = w2s[(s * 8 + tg)     * W2_S + n0];
            b[nf][1] = w2s[(s * 8 + tg + 4) * W2_S + n0];
        }
#pragma unroll
        for (int mf = 0; mf < 2; mf++)
#pragma unroll
            for (int nf = 0; nf < 4; nf++) mma_f16(c2[mf][nf], a[mf], b[nf]);
    }
    const size_t sb = (size_t)blockIdx.x * (EXPM ? NASSIGN : NTOK) * MDIM;
#pragma unroll
    for (int mf = 0; mf < 2; mf++)
#pragma unroll
        for (int nf = 0; nf < 4; nf++) {
            const int col = wn2 * 32 + nf * 8 + 2 * tg;
            const int r0  = wm2 * 32 + mf * 16 + g;
#pragma unroll
            for (int h = 0; h < 2; h++) {
                const int row = r0 + h * 8;
                if (EXPM) {
                    if (bm0 + row < cnt) {
                        const int i = bucket[e * ECAP + bm0 + row];
                        *(float2*)&Cpart[sb + (size_t)i * MDIM + col] =
                            make_float2(c2[mf][nf][h * 2 + 0], c2[mf][nf][h * 2 + 1]);
                    }
                } else {
                    *(float2*)&Cpart[sb + (size_t)(bm0 + row) * MDIM + col] =
                        make_float2(c2[mf][nf][h * 2 + 0], c2[mf][nf][h * 2 + 1]);
                }
            }
        }
}

// ---------------------------------------------------------------------------
// Plain GEMM BK=64 halfs, 3 stages. MODE 0: dec (fp32 out). MODE 1: c2s (half out).
// ---------------------------------------------------------------------------
template<int MODE>
__global__ __launch_bounds__(256, 2)
void mma_gemm(const __half* __restrict__ A, const uint32_t* __restrict__ Wp,
              const float* __restrict__ bias, void* __restrict__ Cv,
              int K, int Hout)
{
    extern __shared__ uint32_t smw[];
    const int tid = threadIdx.x, lane = tid & 31, w = tid >> 5;
    const int g = lane >> 2, tg = lane & 3;
    const int wm = w >> 2, wn = w & 3;
    const int bm0 = blockIdx.y * BM, bn0 = blockIdx.x * BN;

    float c[4][4][4];
#pragma unroll
    for (int i = 0; i < 4; i++)
#pragma unroll
        for (int j = 0; j < 4; j++)
#pragma unroll
            for (int q = 0; q < 4; q++) c[i][j][q] = 0.0f;

    const int nk = K / 64;
    auto issue = [&](int st, int kt) {
        const int k0 = kt * 64;                    // halfs
        uint32_t* as = smw + st * STG2_W;
        uint32_t* bs = as + BM * AS2;
#pragma unroll
        for (int it = 0; it < 4; it++) {
            int idx = tid + it * 256;
            int r = idx >> 3, c4 = idx & 7;
            cp16(&as[r * AS2 + c4 * 4], A + (size_t)(bm0 + r) * K + k0 + c4 * 8);
        }
#pragma unroll
        for (int it = 0; it < 4; it++) {
            int idx = tid + it * 256;
            int r = idx >> 5, cc = idx & 31;
            cp16(&bs[r * BS2 + cc * 4],
                 &Wp[(size_t)(kt * 32 + r) * Hout + bn0 + cc * 4]);
        }
    };

#pragma unroll
    for (int s = 0; s < ST2 - 1; s++) {
        if (s < nk) issue(s, s);
        cp_commit();
    }
    for (int kt = 0; kt < nk; kt++) {
        cp_wait<ST2 - 2>();
        __syncthreads();
        const int st = kt % ST2;
        const uint32_t* as = smw + st * STG2_W;
        const uint32_t* bs = as + BM * AS2;
#pragma unroll
        for (int ks = 0; ks < 4; ks++) {
            uint32_t a[4][4], b[4][2];
#pragma unroll
            for (int mf = 0; mf < 4; mf++) {
                const int m0 = wm * 64 + mf * 16;
                a[mf][0] = as[(m0 + g)     * AS2 + ks * 8 + tg];
                a[mf][1] = as[(m0 + g + 8) * AS2 + ks * 8 + tg];
                a[mf][2] = as[(m0 + g)     * AS2 + ks * 8 + tg + 4];
                a[mf][3] = as[(m0 + g + 8) * AS2 + ks * 8 + tg + 4];
            }
#pragma unroll
            for (int nf = 0; nf < 4; nf++) {
                const int n0 = wn * 32 + nf * 8 + g;
                b[nf][0] = bs[(ks * 8 + tg)     * BS2 + n0];
                b[nf][1] = bs[(ks * 8 + tg + 4) * BS2 + n0];
            }
#pragma unroll
            for (int mf = 0; mf < 4; mf++)
#pragma unroll
                for (int nf = 0; nf < 4; nf++) mma_f16(c[mf][nf], a[mf], b[nf]);
        }
        const int nxt = kt + ST2 - 1;
        if (nxt < nk) issue(nxt % ST2, nxt);
        cp_commit();
    }

#pragma unroll
    for (int mf = 0; mf < 4; mf++)
#pragma unroll
        for (int nf = 0; nf < 4; nf++) {
            const int col = bn0 + wn * 32 + nf * 8 + 2 * tg;
            const int r0  = bm0 + wm * 64 + mf * 16 + g;
#pragma unroll
            for (int h = 0; h < 2; h++) {
                const int row = r0 + h * 8;
                float v0 = sigf(c[mf][nf][h * 2 + 0] + bias[col]);
                float v1 = sigf(c[mf][nf][h * 2 + 1] + bias[col + 1]);
                if (MODE == 1) {
                    ((uint32_t*)Cv)[(size_t)row * (Hout / 2) + (col >> 1)] = h2u(v0, v1);
                } else {
                    *(float2*)&((float*)Cv)[(size_t)row * Hout + col] = make_float2(v0, v1);
                }
            }
        }
}

// ---------------------------------------------------------------------------
// Router: one warp per token (4 tokens / 128-thread block), __syncwarp only.
// Same summation order as before -> bit-identical gates.
// ---------------------------------------------------------------------------
__global__ void router_kernel(const float* __restrict__ part_s2c,
                              const float* __restrict__ s2c_b,
                              __half* __restrict__ cont,
                              const float* __restrict__ rW1, const float* __restrict__ rb1,
                              const float* __restrict__ rW2, const float* __restrict__ rb2,
                              int* __restrict__ assign_e, float* __restrict__ assign_w)
{
    __shared__ float cs[4][64], hid[4][64], logit[4][8];
    const int wid = threadIdx.x >> 5, lane = threadIdx.x & 31;
    const int n = blockIdx.x * 4 + wid;

#pragma unroll
    for (int j = 0; j < 2; j++) {
        const int t = lane + 32 * j;
        float cv = s2c_b[t];
#pragma unroll
        for (int s = 0; s < S2C_SPLIT; s++)
            cv += part_s2c[(size_t)s * NTOK * MDIM + (size_t)n * MDIM + t];
        cont[(size_t)n * MDIM + t] = __float2half_rn(cv);
        cs[wid][t] = cv;
    }
    __syncwarp();

#pragma unroll
    for (int j = 0; j < 2; j++) {
        const int t = lane + 32 * j;
        float a = rb1[t];
#pragma unroll
        for (int m = 0; m < 64; m++) a = fmaf(cs[wid][m], rW1[m * 64 + t], a);
        hid[wid][t] = tanhf(a);
    }
    __syncwarp();

    if (lane < EEXP) {
        float l = rb2[lane];
#pragma unroll
        for (int j = 0; j < 64; j++) l = fmaf(hid[wid][j], rW2[j * EEXP + lane], l);
        logit[wid][lane] = l;
    }
    __syncwarp();

    if (lane == 0) {
        float mx = logit[wid][0];
        for (int e = 1; e < EEXP; e++) mx = fmaxf(mx, logit[wid][e]);
        float p[EEXP];
        for (int e = 0; e < EEXP; e++) p[e] = expf(logit[wid][e] - mx);
        int i1 = 0;
        for (int e = 1; e < EEXP; e++) if (p[e] > p[i1]) i1 = e;
        int i2 = (i1 == 0) ? 1 : 0;
        for (int e = 0; e < EEXP; e++) if (e != i1 && p[e] > p[i2]) i2 = e;
        const float denom = p[i1] + p[i2];
        const int ids[2] = {i1, i2};
        const float ws[2] = {p[i1] / denom, p[i2] / denom};
#pragma unroll
        for (int k = 0; k < 2; k++) {
            const int i = n * 2 + k;
            assign_e[i] = ids[k];
            assign_w[i] = ws[k];
            const int slot = atomicAdd(&g_count[ids[k]], 1);
            g_bucket[ids[k] * ECAP + slot] = i;
        }
    }
}

__global__ void combine_kernel(const float* __restrict__ part_exp,
                               const int* __restrict__ ae, const float* __restrict__ aw,
                               const float* __restrict__ be2, __half* __restrict__ outflat)
{
    const int i = blockIdx.x * 256 + threadIdx.x;
    const int n = i >> 6, m = i & 63;
    float acc = 0.0f;
#pragma unroll
    for (int k = 0; k < 2; k++) {
        const int idx = 2 * n + k;
        float s = be2[ae[idx] * MDIM + m];
#pragma unroll
        for (int sp = 0; sp < EXP_SPLIT; sp++)
            s += part_exp[(size_t)sp * NASSIGN * MDIM + (size_t)idx * MDIM + m];
        acc = fmaf(aw[idx], s, acc);
    }
    outflat[i] = __float2half_rn(acc);
}

__global__ void layernorm_kernel(const float* __restrict__ x,
                                 const float* __restrict__ g, const float* __restrict__ b,
                                 float* __restrict__ out)
{
    const int n = blockIdx.x, t = threadIdx.x;
    const float* row = x + (size_t)n * DDIM;
    float v[4];
    float s = 0.0f, s2 = 0.0f;
#pragma unroll
    for (int i = 0; i < 4; i++) {
        v[i] = row[t + i * 256];
        s += v[i]; s2 += v[i] * v[i];
    }
#pragma unroll
    for (int o = 16; o > 0; o >>= 1) {
        s  += __shfl_xor_sync(0xFFFFFFFFu, s, o);
        s2 += __shfl_xor_sync(0xFFFFFFFFu, s2, o);
    }
    __shared__ float sh1[8], sh2[8], mu_s, rstd_s;
    const int warp = t >> 5, lane = t & 31;
    if (lane == 0) { sh1[warp] = s; sh2[warp] = s2; }
    __syncthreads();
    if (t == 0) {
        float S = 0.0f, S2 = 0.0f;
        for (int wq = 0; wq < 8; wq++) { S += sh1[wq]; S2 += sh2[wq]; }
        float mu = S / (float)DDIM;
        mu_s = mu;
        rstd_s = rsqrtf(S2 / (float)DDIM - mu * mu + 1e-5f);
    }
    __syncthreads();
    const float mu = mu_s, rstd = rstd_s;
    float* orow = out + (size_t)n * DDIM;
#pragma unroll
    for (int i = 0; i < 4; i++) {
        int col = t + i * 256;
        orow[col] = (v[i] - mu) * rstd * g[col] + b[col];
    }
}

// ---------------------------------------------------------------------------
extern "C" void kernel_launch(void* const* d_in, const int* in_sizes, int n_in,
                              void* d_out, int out_size)
{
    const float* X     = (const float*)d_in[0];
    const float* enc_W = (const float*)d_in[1];
    const float* enc_b = (const float*)d_in[2];
    const float* s2c_W = (const float*)d_in[3];
    const float* s2c_b = (const float*)d_in[4];
    const float* rW1   = (const float*)d_in[5];
    const float* rb1   = (const float*)d_in[6];
    const float* rW2   = (const float*)d_in[7];
    const float* rb2   = (const float*)d_in[8];
    const float* We1   = (const float*)d_in[9];
    const float* be1   = (const float*)d_in[10];
    const float* We2   = (const float*)d_in[11];
    const float* be2   = (const float*)d_in[12];
    const float* c2s_W = (const float*)d_in[13];
    const float* c2s_b = (const float*)d_in[14];
    const float* dec_W = (const float*)d_in[15];
    const float* dec_b = (const float*)d_in[16];
    const float* ln_g  = (const float*)d_in[17];
    const float* ln_b  = (const float*)d_in[18];

    __half *Xh, *cont, *outflat, *spk_moe;
    uint32_t *encWp, *s2cWp, *We1p, *We2p, *c2sWp, *decWp;
    float *part_s2c, *aw, *part_exp, *decoded;
    int *ae, *bucket, *count;
    cudaGetSymbolAddress((void**)&Xh,       g_Xh);
    cudaGetSymbolAddress((void**)&encWp,    g_encWp);
    cudaGetSymbolAddress((void**)&s2cWp,    g_s2cWp);
    cudaGetSymbolAddress((void**)&We1p,     g_We1p);
    cudaGetSymbolAddress((void**)&We2p,     g_We2p);
    cudaGetSymbolAddress((void**)&c2sWp,    g_c2sWp);
    cudaGetSymbolAddress((void**)&decWp,    g_decWp);
    cudaGetSymbolAddress((void**)&part_s2c, g_part_s2c);
    cudaGetSymbolAddress((void**)&cont,     g_cont);
    cudaGetSymbolAddress((void**)&ae,       g_assign_e);
    cudaGetSymbolAddress((void**)&aw,       g_assign_w);
    cudaGetSymbolAddress((void**)&count,    g_count);
    cudaGetSymbolAddress((void**)&bucket,   g_bucket);
    cudaGetSymbolAddress((void**)&part_exp, g_part_exp);
    cudaGetSymbolAddress((void**)&outflat,  g_outflat);
    cudaGetSymbolAddress((void**)&spk_moe,  g_spk_moe);
    cudaGetSymbolAddress((void**)&decoded,  g_decoded);

    auto kEnc = fused_gemm2<false>;
    auto kExp = fused_gemm2<true>;
    auto kC2s = mma_gemm<1>;
    auto kDec = mma_gemm<0>;
    cudaFuncSetAttribute(kEnc, cudaFuncAttributeMaxDynamicSharedMemorySize, FUSED_SMEM);
    cudaFuncSetAttribute(kExp, cudaFuncAttributeMaxDynamicSharedMemorySize, FUSED_SMEM);
    cudaFuncSetAttribute(kC2s, cudaFuncAttributeMaxDynamicSharedMemorySize, PIPE2_SMEM);
    cudaFuncSetAttribute(kDec, cudaFuncAttributeMaxDynamicSharedMemorySize, PIPE2_SMEM);

    // 0) prep: fp16 conversion + k-pair packing + zero counts
    prep_all<<<(PK_TOT + 255) / 256, 256>>>(X, enc_W, s2c_W, We1, We2, c2s_W, dec_W);

    // 1) fused encoder+s2c (K=1024 halfs, 32 K-tiles)
    kEnc<<<dim3(S2C_SPLIT, NTOK / BM), 256, FUSED_SMEM>>>(
        Xh, encWp, enc_b, s2cWp, part_s2c, DDIM, DDIM, HDIM, nullptr, nullptr);

    // 2) routing (warp per token)
    router_kernel<<<NTOK / 4, 128>>>(part_s2c, s2c_b, cont, rW1, rb1, rW2, rb2, ae, aw);

    // 3) fused expert MLP (K=64 halfs, 2 K-tiles)
    kExp<<<dim3(EXP_SPLIT, ECAP / BM, EEXP), 256, FUSED_SMEM>>>(
        cont, We1p, be1, We2p, part_exp, MDIM, MDIM, HHALF, bucket, count);

    // 4) combine
    combine_kernel<<<(NTOK * MDIM) / 256, 256>>>(part_exp, ae, aw, be2, outflat);

    // 5) c2s: sigmoid -> half spk_moe (K=64, 1 K-tile)
    kC2s<<<dim3(HDIM / BN, NTOK / BM), 256, PIPE2_SMEM>>>(
        outflat, c2sWp, c2s_b, spk_moe, MDIM, HDIM);

    // 6) decoder: sigmoid -> fp32 decoded (K=2048, 32 K-tiles)
    kDec<<<dim3(DDIM / BN, NTOK / BM), 256, PIPE2_SMEM>>>(
        spk_moe, decWp, dec_b, decoded, HDIM, DDIM);

    // 7) layernorm -> d_out
    layernorm_kernel<<<NTOK, 256>>>(decoded, ln_g, ln_b, (float*)d_out);
}

// round 12
// speedup vs baseline: 1.7198x; 1.0359x over previous
#include <cuda_runtime.h>
#include <cuda_fp16.h>
#include <math.h>
#include <stdint.h>

#define NTOK 8192
#define DDIM 1024
#define HDIM 2048
#define MDIM 64
#define EEXP 8
#define HHALF 1024
#define ECAP 8192
#define NASSIGN (NTOK * 2)
#define S2C_SPLIT 16
#define EXP_SPLIT 8

// ---------------------------------------------------------------------------
// fp16 buffers: A-side natural half rows; B-side k-pair-packed half2 words
// ---------------------------------------------------------------------------
__device__ __half   g_Xh[(size_t)NTOK * DDIM];
__device__ uint32_t g_encWp[(size_t)(DDIM / 2) * HDIM];
__device__ uint32_t g_s2cWp[(size_t)(HDIM / 2) * MDIM];
__device__ uint32_t g_We1p[(size_t)EEXP * (MDIM / 2) * HHALF];
__device__ uint32_t g_We2p[(size_t)EEXP * (HHALF / 2) * MDIM];
__device__ uint32_t g_c2sWp[(size_t)(MDIM / 2) * HDIM];
__device__ uint32_t g_decWp[(size_t)(HDIM / 2) * DDIM];

__device__ float  g_part_s2c[(size_t)S2C_SPLIT * NTOK * MDIM];
__device__ __half g_cont[(size_t)NTOK * MDIM];
__device__ int    g_assign_e[NASSIGN];
__device__ float  g_assign_w[NASSIGN];
__device__ int    g_count[EEXP];
__device__ int    g_bucket[EEXP * ECAP];
__device__ float  g_part_exp[(size_t)EXP_SPLIT * NASSIGN * MDIM];
__device__ __half g_outflat[(size_t)NTOK * MDIM];
__device__ __half g_spk_moe[(size_t)NTOK * HDIM];
__device__ float  g_decoded[(size_t)NTOK * DDIM];

__device__ __forceinline__ float sigf(float x) { return 1.0f / (1.0f + expf(-x)); }
__device__ __forceinline__ void cp16(void* dst, const void* src) {
    unsigned d = (unsigned)__cvta_generic_to_shared(dst);
    asm volatile("cp.async.cg.shared.global [%0], [%1], 16;\n" :: "r"(d), "l"(src));
}
__device__ __forceinline__ void cp_commit() { asm volatile("cp.async.commit_group;\n"); }
template<int N> __device__ __forceinline__ void cp_wait() {
    asm volatile("cp.async.wait_group %0;\n" :: "n"(N));
}
__device__ __forceinline__ void mma_f16(float c[4], const uint32_t a[4], const uint32_t b[2]) {
    asm volatile(
        "mma.sync.aligned.m16n8k16.row.col.f32.f16.f16.f32 "
        "{%0,%1,%2,%3}, {%4,%5,%6,%7}, {%8,%9}, {%0,%1,%2,%3};\n"
        : "+f"(c[0]), "+f"(c[1]), "+f"(c[2]), "+f"(c[3])
        : "r"(a[0]), "r"(a[1]), "r"(a[2]), "r"(a[3]), "r"(b[0]), "r"(b[1]));
}
// Warp-collective 16x16 b16 A-fragment load; register contents bit-identical
// to the 4x LDS.32 pattern (row = m0 + lane&15 ; word col = base + (lane>>4)*4).
__device__ __forceinline__ void ldsm_x4(uint32_t r[4], uint32_t saddr) {
    asm volatile("ldmatrix.sync.aligned.m8n8.x4.shared.b16 {%0,%1,%2,%3}, [%4];"
                 : "=r"(r[0]), "=r"(r[1]), "=r"(r[2]), "=r"(r[3]) : "r"(saddr));
}
__device__ __forceinline__ uint32_t smem_u32(const void* p) {
    return (uint32_t)__cvta_generic_to_shared(p);
}
__device__ __forceinline__ uint32_t h2u(float a, float b) {
    __half2 h = __floats2half2_rn(a, b);
    return *(uint32_t*)&h;
}

// fused (enc/expert): BK=32 halfs (16 kp-words), 4 stages.
#define BM 128
#define BN 128
#define AS 20
#define BS1 136
#define STAGES 4
#define STG_W (BM * AS + 16 * BS1)          // 4736 words / stage
#define W2_OFF (STAGES * STG_W)             // 18944
#define W2_S 72
#define SPIKE_S 68
#define FUSED_SMEM ((W2_OFF + 64 * W2_S) * 4)   // 94208 B

// plain (c2s/dec): BK=64 halfs (32 kp-words), 3 stages.
#define AS2 36
#define BS2 136
#define ST2 3
#define STG2_W (BM * AS2 + 32 * BS2)        // 8960 words / stage
#define PIPE2_SMEM (ST2 * STG2_W * 4)       // 107520 B

// ---------------------------------------------------------------------------
// Prep: X -> half; weights -> k-pair-packed half2 words.
// ---------------------------------------------------------------------------
#define PK_X   0UL
#define PK_EW  4194304UL
#define PK_SW  5242880UL
#define PK_W1  5308416UL
#define PK_W2  5570560UL
#define PK_CW  5832704UL
#define PK_DW  5898240UL
#define PK_TOT 6946816UL

__global__ void prep_all(const float* __restrict__ X,   const float* __restrict__ encW,
                         const float* __restrict__ s2cW, const float* __restrict__ We1,
                         const float* __restrict__ We2,  const float* __restrict__ c2sW,
                         const float* __restrict__ decW)
{
    if (blockIdx.x == 0 && threadIdx.x < EEXP) g_count[threadIdx.x] = 0;
    const size_t f = (size_t)blockIdx.x * 256 + threadIdx.x;
    if (f >= PK_TOT) return;
    if (f < PK_EW) {
        float2 v = *(const float2*)&X[2 * f];
        ((__half2*)g_Xh)[f] = __floats2half2_rn(v.x, v.y);
        return;
    }
    const float* src; uint32_t* dst; size_t local; int N;
    if      (f < PK_SW) { src = encW; dst = g_encWp; local = f - PK_EW; N = HDIM; }
    else if (f < PK_W1) { src = s2cW; dst = g_s2cWp; local = f - PK_SW; N = MDIM; }
    else if (f < PK_W2) { src = We1;  dst = g_We1p;  local = f - PK_W1; N = HHALF; }
    else if (f < PK_CW) { src = We2;  dst = g_We2p;  local = f - PK_W2; N = MDIM; }
    else if (f < PK_DW) { src = c2sW; dst = g_c2sWp; local = f - PK_CW; N = HDIM; }
    else                { src = decW; dst = g_decWp; local = f - PK_DW; N = DDIM; }
    const size_t kp = local / N, n = local % N;
    const float w0 = src[(2 * kp) * (size_t)N + n];
    const float w1 = src[(2 * kp + 1) * (size_t)N + n];
    ((__half2*)dst)[local] = __floats2half2_rn(w0, w1);
}

// ---------------------------------------------------------------------------
// Fused GEMM+GEMM, fp16, BK=32 halfs, ldmatrix A fragments.
// ---------------------------------------------------------------------------
template<bool EXPM>
__global__ __launch_bounds__(256, 2)
void fused_gemm2(const __half* __restrict__ A, const uint32_t* __restrict__ W1p,
                 const float* __restrict__ b1, const uint32_t* __restrict__ W2p,
                 float* __restrict__ Cpart, int K, int lda, int ldw1,
                 const int* __restrict__ bucket, const int* __restrict__ count)
{
    extern __shared__ uint32_t smw[];
    uint32_t* spike = smw;
    uint32_t* w2s   = smw + W2_OFF;

    const int tid = threadIdx.x, lane = tid & 31, w = tid >> 5;
    const int g = lane >> 2, tg = lane & 3;
    const int wm = w >> 2, wn = w & 3;
    const int rowsel = lane & 15;              // ldmatrix lane row
    const int colsel = (lane >> 4) << 2;       // ldmatrix lane col (words)
    const int bm0 = blockIdx.y * BM, bn0 = blockIdx.x * BN;
    const int e = EXPM ? blockIdx.z : 0;

    int cnt = 0;
    if (EXPM) {
        cnt = count[e];
        if (bm0 >= cnt) return;
    }

    const uint32_t* W1 = EXPM ? W1p + (size_t)e * (MDIM / 2) * HHALF : W1p;
    const float*    bb = EXPM ? b1 + (size_t)e * HHALF : b1;
    const uint32_t* W2 = EXPM ? W2p + (size_t)e * (HHALF / 2) * MDIM : W2p;

    size_t aoff[2];
#pragma unroll
    for (int it = 0; it < 2; it++) {
        const int r = (tid + it * 256) >> 2;
        const int grow = bm0 + r;
        if (EXPM) {
            const int rr = (grow < cnt) ? grow : (cnt - 1);
            aoff[it] = (size_t)(bucket[e * ECAP + rr] >> 1) * MDIM;
        } else {
            aoff[it] = (size_t)grow * lda;
        }
    }

#pragma unroll
    for (int it = 0; it < 4; it++) {
        int idx = tid + it * 256;
        int r = idx >> 4, c = idx & 15;
        cp16(&w2s[r * W2_S + c * 4], &W2[(size_t)(bn0 / 2 + r) * MDIM + c * 4]);
    }
    cp_commit();

    float c[4][4][4];
#pragma unroll
    for (int i = 0; i < 4; i++)
#pragma unroll
        for (int j = 0; j < 4; j++)
#pragma unroll
            for (int q = 0; q < 4; q++) c[i][j][q] = 0.0f;

    const int nk = K / 32;
    auto issue = [&](int st, int kt) {
        const int k0 = kt * 32;
        uint32_t* as = smw + st * STG_W;
        uint32_t* bs = as + BM * AS;
#pragma unroll
        for (int it = 0; it < 2; it++) {
            int idx = tid + it * 256;
            int r = idx >> 2, c4 = idx & 3;
            cp16(&as[r * AS + c4 * 4], A + aoff[it] + k0 + c4 * 8);
        }
#pragma unroll
        for (int it = 0; it < 2; it++) {
            int idx = tid + it * 256;
            int r = idx >> 5, cc = idx & 31;
            cp16(&bs[r * BS1 + cc * 4],
                 &W1[(size_t)(kt * 16 + r) * ldw1 + bn0 + cc * 4]);
        }
    };

#pragma unroll
    for (int s = 0; s < STAGES - 1; s++) {
        if (s < nk) issue(s, s);
        cp_commit();
    }
    for (int kt = 0; kt < nk; kt++) {
        cp_wait<STAGES - 2>();
        __syncthreads();
        const int st = kt % STAGES;
        const uint32_t* as = smw + st * STG_W;
        const uint32_t* bs = as + BM * AS;
        const uint32_t as_b = smem_u32(as);
#pragma unroll
        for (int ks = 0; ks < 2; ks++) {
            uint32_t a[4][4], b[4][2];
#pragma unroll
            for (int mf = 0; mf < 4; mf++) {
                const int m0 = wm * 64 + mf * 16;
                ldsm_x4(a[mf], as_b + (((m0 + rowsel) * AS + ks * 8 + colsel) << 2));
            }
#pragma unroll
            for (int nf = 0; nf < 4; nf++) {
                const int n0 = wn * 32 + nf * 8 + g;
                b[nf][0] = bs[(ks * 8 + tg)     * BS1 + n0];
                b[nf][1] = bs[(ks * 8 + tg + 4) * BS1 + n0];
            }
#pragma unroll
            for (int mf = 0; mf < 4; mf++)
#pragma unroll
                for (int nf = 0; nf < 4; nf++) mma_f16(c[mf][nf], a[mf], b[nf]);
        }
        const int nxt = kt + STAGES - 1;
        if (nxt < nk) issue(nxt % STAGES, nxt);
        cp_commit();
    }

    cp_wait<0>();
    __syncthreads();
#pragma unroll
    for (int mf = 0; mf < 4; mf++)
#pragma unroll
        for (int nf = 0; nf < 4; nf++) {
            const int col = wn * 32 + nf * 8 + 2 * tg;
            const int r0  = wm * 64 + mf * 16 + g;
#pragma unroll
            for (int h = 0; h < 2; h++) {
                const int row = r0 + h * 8;
                float v0 = c[mf][nf][h * 2 + 0] + bb[bn0 + col];
                float v1 = c[mf][nf][h * 2 + 1] + bb[bn0 + col + 1];
                if (EXPM) { v0 = fmaxf(v0, 0.0f); v1 = fmaxf(v1, 0.0f); }
                else      { v0 = sigf(v0);        v1 = sigf(v1); }
                spike[row * SPIKE_S + (col >> 1)] = h2u(v0, v1);
            }
        }
    __syncthreads();

    // mini GEMM: part[128x64] = spike(128x128 halfs) @ w2s
    const int wm2 = w >> 1, wn2 = w & 1;
    const uint32_t spike_b = smem_u32(spike);
    float c2[2][4][4];
#pragma unroll
    for (int i = 0; i < 2; i++)
#pragma unroll
        for (int j = 0; j < 4; j++)
#pragma unroll
            for (int q = 0; q < 4; q++) c2[i][j][q] = 0.0f;
#pragma unroll
    for (int s = 0; s < 8; s++) {
        uint32_t a[2][4], b[4][2];
#pragma unroll
        for (int mf = 0; mf < 2; mf++) {
            const int m0 = wm2 * 32 + mf * 16;
            ldsm_x4(a[mf], spike_b + (((m0 + rowsel) * SPIKE_S + s * 8 + colsel) << 2));
        }
#pragma unroll
        for (int nf = 0; nf < 4; nf++) {
            const int n0 = wn2 * 32 + nf * 8 + g;
            b[nf][0] = w2s[(s * 8 + tg)     * W2_S + n0];
            b[nf][1] = w2s[(s * 8 + tg + 4) * W2_S + n0];
        }
#pragma unroll
        for (int mf = 0; mf < 2; mf++)
#pragma unroll
            for (int nf = 0; nf < 4; nf++) mma_f16(c2[mf][nf], a[mf], b[nf]);
    }
    const size_t sb = (size_t)blockIdx.x * (EXPM ? NASSIGN : NTOK) * MDIM;
#pragma unroll
    for (int mf = 0; mf < 2; mf++)
#pragma unroll
        for (int nf = 0; nf < 4; nf++) {
            const int col = wn2 * 32 + nf * 8 + 2 * tg;
            const int r0  = wm2 * 32 + mf * 16 + g;
#pragma unroll
            for (int h = 0; h < 2; h++) {
                const int row = r0 + h * 8;
                if (EXPM) {
                    if (bm0 + row < cnt) {
                        const int i = bucket[e * ECAP + bm0 + row];
                        *(float2*)&Cpart[sb + (size_t)i * MDIM + col] =
                            make_float2(c2[mf][nf][h * 2 + 0], c2[mf][nf][h * 2 + 1]);
                    }
                } else {
                    *(float2*)&Cpart[sb + (size_t)(bm0 + row) * MDIM + col] =
                        make_float2(c2[mf][nf][h * 2 + 0], c2[mf][nf][h * 2 + 1]);
                }
            }
        }
}

// ---------------------------------------------------------------------------
// Plain GEMM BK=64 halfs, 3 stages, ldmatrix A. MODE 0: dec. MODE 1: c2s.
// ---------------------------------------------------------------------------
template<int MODE>
__global__ __launch_bounds__(256, 2)
void mma_gemm(const __half* __restrict__ A, const uint32_t* __restrict__ Wp,
              const float* __restrict__ bias, void* __restrict__ Cv,
              int K, int Hout)
{
    extern __shared__ uint32_t smw[];
    const int tid = threadIdx.x, lane = tid & 31, w = tid >> 5;
    const int g = lane >> 2, tg = lane & 3;
    const int wm = w >> 2, wn = w & 3;
    const int rowsel = lane & 15;
    const int colsel = (lane >> 4) << 2;
    const int bm0 = blockIdx.y * BM, bn0 = blockIdx.x * BN;

    float c[4][4][4];
#pragma unroll
    for (int i = 0; i < 4; i++)
#pragma unroll
        for (int j = 0; j < 4; j++)
#pragma unroll
            for (int q = 0; q < 4; q++) c[i][j][q] = 0.0f;

    const int nk = K / 64;
    auto issue = [&](int st, int kt) {
        const int k0 = kt * 64;
        uint32_t* as = smw + st * STG2_W;
        uint32_t* bs = as + BM * AS2;
#pragma unroll
        for (int it = 0; it < 4; it++) {
            int idx = tid + it * 256;
            int r = idx >> 3, c4 = idx & 7;
            cp16(&as[r * AS2 + c4 * 4], A + (size_t)(bm0 + r) * K + k0 + c4 * 8);
        }
#pragma unroll
        for (int it = 0; it < 4; it++) {
            int idx = tid + it * 256;
            int r = idx >> 5, cc = idx & 31;
            cp16(&bs[r * BS2 + cc * 4],
                 &Wp[(size_t)(kt * 32 + r) * Hout + bn0 + cc * 4]);
        }
    };

#pragma unroll
    for (int s = 0; s < ST2 - 1; s++) {
        if (s < nk) issue(s, s);
        cp_commit();
    }
    for (int kt = 0; kt < nk; kt++) {
        cp_wait<ST2 - 2>();
        __syncthreads();
        const int st = kt % ST2;
        const uint32_t* as = smw + st * STG2_W;
        const uint32_t* bs = as + BM * AS2;
        const uint32_t as_b = smem_u32(as);
#pragma unroll
        for (int ks = 0; ks < 4; ks++) {
            uint32_t a[4][4], b[4][2];
#pragma unroll
            for (int mf = 0; mf < 4; mf++) {
                const int m0 = wm * 64 + mf * 16;
                ldsm_x4(a[mf], as_b + (((m0 + rowsel) * AS2 + ks * 8 + colsel) << 2));
            }
#pragma unroll
            for (int nf = 0; nf < 4; nf++) {
                const int n0 = wn * 32 + nf * 8 + g;
                b[nf][0] = bs[(ks * 8 + tg)     * BS2 + n0];
                b[nf][1] = bs[(ks * 8 + tg + 4) * BS2 + n0];
            }
#pragma unroll
            for (int mf = 0; mf < 4; mf++)
#pragma unroll
                for (int nf = 0; nf < 4; nf++) mma_f16(c[mf][nf], a[mf], b[nf]);
        }
        const int nxt = kt + ST2 - 1;
        if (nxt < nk) issue(nxt % ST2, nxt);
        cp_commit();
    }

#pragma unroll
    for (int mf = 0; mf < 4; mf++)
#pragma unroll
        for (int nf = 0; nf < 4; nf++) {
            const int col = bn0 + wn * 32 + nf * 8 + 2 * tg;
            const int r0  = bm0 + wm * 64 + mf * 16 + g;
#pragma unroll
            for (int h = 0; h < 2; h++) {
                const int row = r0 + h * 8;
                float v0 = sigf(c[mf][nf][h * 2 + 0] + bias[col]);
                float v1 = sigf(c[mf][nf][h * 2 + 1] + bias[col + 1]);
                if (MODE == 1) {
                    ((uint32_t*)Cv)[(size_t)row * (Hout / 2) + (col >> 1)] = h2u(v0, v1);
                } else {
                    *(float2*)&((float*)Cv)[(size_t)row * Hout + col] = make_float2(v0, v1);
                }
            }
        }
}

// ---------------------------------------------------------------------------
// Router: one warp per token, __syncwarp only (bit-same gates).
// ---------------------------------------------------------------------------
__global__ void router_kernel(const float* __restrict__ part_s2c,
                              const float* __restrict__ s2c_b,
                              __half* __restrict__ cont,
                              const float* __restrict__ rW1, const float* __restrict__ rb1,
                              const float* __restrict__ rW2, const float* __restrict__ rb2,
                              int* __restrict__ assign_e, float* __restrict__ assign_w)
{
    __shared__ float cs[4][64], hid[4][64], logit[4][8];
    const int wid = threadIdx.x >> 5, lane = threadIdx.x & 31;
    const int n = blockIdx.x * 4 + wid;

#pragma unroll
    for (int j = 0; j < 2; j++) {
        const int t = lane + 32 * j;
        float cv = s2c_b[t];
#pragma unroll
        for (int s = 0; s < S2C_SPLIT; s++)
            cv += part_s2c[(size_t)s * NTOK * MDIM + (size_t)n * MDIM + t];
        cont[(size_t)n * MDIM + t] = __float2half_rn(cv);
        cs[wid][t] = cv;
    }
    __syncwarp();

#pragma unroll
    for (int j = 0; j < 2; j++) {
        const int t = lane + 32 * j;
        float a = rb1[t];
#pragma unroll
        for (int m = 0; m < 64; m++) a = fmaf(cs[wid][m], rW1[m * 64 + t], a);
        hid[wid][t] = tanhf(a);
    }
    __syncwarp();

    if (lane < EEXP) {
        float l = rb2[lane];
#pragma unroll
        for (int j = 0; j < 64; j++) l = fmaf(hid[wid][j], rW2[j * EEXP + lane], l);
        logit[wid][lane] = l;
    }
    __syncwarp();

    if (lane == 0) {
        float mx = logit[wid][0];
        for (int e = 1; e < EEXP; e++) mx = fmaxf(mx, logit[wid][e]);
        float p[EEXP];
        for (int e = 0; e < EEXP; e++) p[e] = expf(logit[wid][e] - mx);
        int i1 = 0;
        for (int e = 1; e < EEXP; e++) if (p[e] > p[i1]) i1 = e;
        int i2 = (i1 == 0) ? 1 : 0;
        for (int e = 0; e < EEXP; e++) if (e != i1 && p[e] > p[i2]) i2 = e;
        const float denom = p[i1] + p[i2];
        const int ids[2] = {i1, i2};
        const float ws[2] = {p[i1] / denom, p[i2] / denom};
#pragma unroll
        for (int k = 0; k < 2; k++) {
            const int i = n * 2 + k;
            assign_e[i] = ids[k];
            assign_w[i] = ws[k];
            const int slot = atomicAdd(&g_count[ids[k]], 1);
            g_bucket[ids[k] * ECAP + slot] = i;
        }
    }
}

__global__ void combine_kernel(const float* __restrict__ part_exp,
                               const int* __restrict__ ae, const float* __restrict__ aw,
                               const float* __restrict__ be2, __half* __restrict__ outflat)
{
    const int i = blockIdx.x * 256 + threadIdx.x;
    const int n = i >> 6, m = i & 63;
    float acc = 0.0f;
#pragma unroll
    for (int k = 0; k < 2; k++) {
        const int idx = 2 * n + k;
        float s = be2[ae[idx] * MDIM + m];
#pragma unroll
        for (int sp = 0; sp < EXP_SPLIT; sp++)
            s += part_exp[(size_t)sp * NASSIGN * MDIM + (size_t)idx * MDIM + m];
        acc = fmaf(aw[idx], s, acc);
    }
    outflat[i] = __float2half_rn(acc);
}

__global__ void layernorm_kernel(const float* __restrict__ x,
                                 const float* __restrict__ g, const float* __restrict__ b,
                                 float* __restrict__ out)
{
    const int n = blockIdx.x, t = threadIdx.x;
    const float* row = x + (size_t)n * DDIM;
    float v[4];
    float s = 0.0f, s2 = 0.0f;
#pragma unroll
    for (int i = 0; i < 4; i++) {
        v[i] = row[t + i * 256];
        s += v[i]; s2 += v[i] * v[i];
    }
#pragma unroll
    for (int o = 16; o > 0; o >>= 1) {
        s  += __shfl_xor_sync(0xFFFFFFFFu, s, o);
        s2 += __shfl_xor_sync(0xFFFFFFFFu, s2, o);
    }
    __shared__ float sh1[8], sh2[8], mu_s, rstd_s;
    const int warp = t >> 5, lane = t & 31;
    if (lane == 0) { sh1[warp] = s; sh2[warp] = s2; }
    __syncthreads();
    if (t == 0) {
        float S = 0.0f, S2 = 0.0f;
        for (int wq = 0; wq < 8; wq++) { S += sh1[wq]; S2 += sh2[wq]; }
        float mu = S / (float)DDIM;
        mu_s = mu;
        rstd_s = rsqrtf(S2 / (float)DDIM - mu * mu + 1e-5f);
    }
    __syncthreads();
    const float mu = mu_s, rstd = rstd_s;
    float* orow = out + (size_t)n * DDIM;
#pragma unroll
    for (int i = 0; i < 4; i++) {
        int col = t + i * 256;
        orow[col] = (v[i] - mu) * rstd * g[col] + b[col];
    }
}

// ---------------------------------------------------------------------------
extern "C" void kernel_launch(void* const* d_in, const int* in_sizes, int n_in,
                              void* d_out, int out_size)
{
    const float* X     = (const float*)d_in[0];
    const float* enc_W = (const float*)d_in[1];
    const float* enc_b = (const float*)d_in[2];
    const float* s2c_W = (const float*)d_in[3];
    const float* s2c_b = (const float*)d_in[4];
    const float* rW1   = (const float*)d_in[5];
    const float* rb1   = (const float*)d_in[6];
    const float* rW2   = (const float*)d_in[7];
    const float* rb2   = (const float*)d_in[8];
    const float* We1   = (const float*)d_in[9];
    const float* be1   = (const float*)d_in[10];
    const float* We2   = (const float*)d_in[11];
    const float* be2   = (const float*)d_in[12];
    const float* c2s_W = (const float*)d_in[13];
    const float* c2s_b = (const float*)d_in[14];
    const float* dec_W = (const float*)d_in[15];
    const float* dec_b = (const float*)d_in[16];
    const float* ln_g  = (const float*)d_in[17];
    const float* ln_b  = (const float*)d_in[18];

    __half *Xh, *cont, *outflat, *spk_moe;
    uint32_t *encWp, *s2cWp, *We1p, *We2p, *c2sWp, *decWp;
    float *part_s2c, *aw, *part_exp, *decoded;
    int *ae, *bucket, *count;
    cudaGetSymbolAddress((void**)&Xh,       g_Xh);
    cudaGetSymbolAddress((void**)&encWp,    g_encWp);
    cudaGetSymbolAddress((void**)&s2cWp,    g_s2cWp);
    cudaGetSymbolAddress((void**)&We1p,     g_We1p);
    cudaGetSymbolAddress((void**)&We2p,     g_We2p);
    cudaGetSymbolAddress((void**)&c2sWp,    g_c2sWp);
    cudaGetSymbolAddress((void**)&decWp,    g_decWp);
    cudaGetSymbolAddress((void**)&part_s2c, g_part_s2c);
    cudaGetSymbolAddress((void**)&cont,     g_cont);
    cudaGetSymbolAddress((void**)&ae,       g_assign_e);
    cudaGetSymbolAddress((void**)&aw,       g_assign_w);
    cudaGetSymbolAddress((void**)&count,    g_count);
    cudaGetSymbolAddress((void**)&bucket,   g_bucket);
    cudaGetSymbolAddress((void**)&part_exp, g_part_exp);
    cudaGetSymbolAddress((void**)&outflat,  g_outflat);
    cudaGetSymbolAddress((void**)&spk_moe,  g_spk_moe);
    cudaGetSymbolAddress((void**)&decoded,  g_decoded);

    auto kEnc = fused_gemm2<false>;
    auto kExp = fused_gemm2<true>;
    auto kC2s = mma_gemm<1>;
    auto kDec = mma_gemm<0>;
    cudaFuncSetAttribute(kEnc, cudaFuncAttributeMaxDynamicSharedMemorySize, FUSED_SMEM);
    cudaFuncSetAttribute(kExp, cudaFuncAttributeMaxDynamicSharedMemorySize, FUSED_SMEM);
    cudaFuncSetAttribute(kC2s, cudaFuncAttributeMaxDynamicSharedMemorySize, PIPE2_SMEM);
    cudaFuncSetAttribute(kDec, cudaFuncAttributeMaxDynamicSharedMemorySize, PIPE2_SMEM);

    // 0) prep: fp16 conversion + k-pair packing + zero counts
    prep_all<<<(PK_TOT + 255) / 256, 256>>>(X, enc_W, s2c_W, We1, We2, c2s_W, dec_W);

    // 1) fused encoder+s2c (K=1024 halfs, 32 K-tiles)
    kEnc<<<dim3(S2C_SPLIT, NTOK / BM), 256, FUSED_SMEM>>>(
        Xh, encWp, enc_b, s2cWp, part_s2c, DDIM, DDIM, HDIM, nullptr, nullptr);

    // 2) routing (warp per token)
    router_kernel<<<NTOK / 4, 128>>>(part_s2c, s2c_b, cont, rW1, rb1, rW2, rb2, ae, aw);

    // 3) fused expert MLP (K=64 halfs, 2 K-tiles)
    kExp<<<dim3(EXP_SPLIT, ECAP / BM, EEXP), 256, FUSED_SMEM>>>(
        cont, We1p, be1, We2p, part_exp, MDIM, MDIM, HHALF, bucket, count);

    // 4) combine
    combine_kernel<<<(NTOK * MDIM) / 256, 256>>>(part_exp, ae, aw, be2, outflat);

    // 5) c2s: sigmoid -> half spk_moe (K=64)
    kC2s<<<dim3(HDIM / BN, NTOK / BM), 256, PIPE2_SMEM>>>(
        outflat, c2sWp, c2s_b, spk_moe, MDIM, HDIM);

    // 6) decoder: sigmoid -> fp32 decoded (K=2048, 32 K-tiles)
    kDec<<<dim3(DDIM / BN, NTOK / BM), 256, PIPE2_SMEM>>>(
        spk_moe, decWp, dec_b, decoded, HDIM, DDIM);

    // 7) layernorm -> d_out
    layernorm_kernel<<<NTOK, 256>>>(decoded, ln_g, ln_b, (float*)d_out);
}

// round 13
// speedup vs baseline: 1.7507x; 1.0180x over previous
#include <cuda_runtime.h>
#include <cuda_fp16.h>
#include <math.h>
#include <stdint.h>

#define NTOK 8192
#define DDIM 1024
#define HDIM 2048
#define MDIM 64
#define EEXP 8
#define HHALF 1024
#define ECAP 8192
#define NASSIGN (NTOK * 2)
#define S2C_SPLIT 16
#define EXP_SPLIT 8

// ---------------------------------------------------------------------------
// fp16 buffers: A-side natural half rows; B-side k-pair-packed half2 words
// ---------------------------------------------------------------------------
__device__ __half   g_Xh[(size_t)NTOK * DDIM];
__device__ uint32_t g_encWp[(size_t)(DDIM / 2) * HDIM];
__device__ uint32_t g_s2cWp[(size_t)(HDIM / 2) * MDIM];
__device__ uint32_t g_We1p[(size_t)EEXP * (MDIM / 2) * HHALF];
__device__ uint32_t g_We2p[(size_t)EEXP * (HHALF / 2) * MDIM];
__device__ uint32_t g_c2sWp[(size_t)(MDIM / 2) * HDIM];
__device__ uint32_t g_decWp[(size_t)(HDIM / 2) * DDIM];

__device__ float  g_part_s2c[(size_t)S2C_SPLIT * NTOK * MDIM];
__device__ __half g_cont[(size_t)NTOK * MDIM];
__device__ int    g_assign_e[NASSIGN];
__device__ float  g_assign_w[NASSIGN];
__device__ int    g_count[EEXP];
__device__ int    g_bucket[EEXP * ECAP];
__device__ float  g_part_exp[(size_t)EXP_SPLIT * NASSIGN * MDIM];
__device__ __half g_outflat[(size_t)NTOK * MDIM];
__device__ __half g_spk_moe[(size_t)NTOK * HDIM];
__device__ float  g_decoded[(size_t)NTOK * DDIM];

__device__ __forceinline__ float sigf(float x) { return 1.0f / (1.0f + expf(-x)); }
__device__ __forceinline__ void cp16(void* dst, const void* src) {
    unsigned d = (unsigned)__cvta_generic_to_shared(dst);
    asm volatile("cp.async.cg.shared.global [%0], [%1], 16;\n" :: "r"(d), "l"(src));
}
__device__ __forceinline__ void cp_commit() { asm volatile("cp.async.commit_group;\n"); }
template<int N> __device__ __forceinline__ void cp_wait() {
    asm volatile("cp.async.wait_group %0;\n" :: "n"(N));
}
__device__ __forceinline__ void mma_f16(float c[4], const uint32_t a[4], const uint32_t b[2]) {
    asm volatile(
        "mma.sync.aligned.m16n8k16.row.col.f32.f16.f16.f32 "
        "{%0,%1,%2,%3}, {%4,%5,%6,%7}, {%8,%9}, {%0,%1,%2,%3};\n"
        : "+f"(c[0]), "+f"(c[1]), "+f"(c[2]), "+f"(c[3])
        : "r"(a[0]), "r"(a[1]), "r"(a[2]), "r"(a[3]), "r"(b[0]), "r"(b[1]));
}
__device__ __forceinline__ void ldsm_x4(uint32_t r[4], uint32_t saddr) {
    asm volatile("ldmatrix.sync.aligned.m8n8.x4.shared.b16 {%0,%1,%2,%3}, [%4];"
                 : "=r"(r[0]), "=r"(r[1]), "=r"(r[2]), "=r"(r[3]) : "r"(saddr));
}
__device__ __forceinline__ uint32_t smem_u32(const void* p) {
    return (uint32_t)__cvta_generic_to_shared(p);
}
__device__ __forceinline__ uint32_t h2u(float a, float b) {
    __half2 h = __floats2half2_rn(a, b);
    return *(uint32_t*)&h;
}

// Unified GEMM geometry: BK=64 halfs (32 kp-words), 3 stages.
// A [m][kp] stride 36 words; B [kp][n] stride 136 words.
#define BM 128
#define BN 128
#define AS2 36
#define BS2 136
#define ST2 3
#define STG2_W (BM * AS2 + 32 * BS2)        // 8960 words / stage
#define PIPE2_SMEM (ST2 * STG2_W * 4)       // 107520 B
// fused-kernel epilogue regions alias dead pipeline stages:
#define W2_S 72
#define SPIKE_S 68
// w2s at stage-0 (needs 64*72=4608 <= 8960); spike at stage-1 (128*68=8704 <= 8960)
#define SPIKE_OFF STG2_W

// ---------------------------------------------------------------------------
// Prep: X -> half; weights -> k-pair-packed half2 words.
// ---------------------------------------------------------------------------
#define PK_X   0UL
#define PK_EW  4194304UL
#define PK_SW  5242880UL
#define PK_W1  5308416UL
#define PK_W2  5570560UL
#define PK_CW  5832704UL
#define PK_DW  5898240UL
#define PK_TOT 6946816UL

__global__ void prep_all(const float* __restrict__ X,   const float* __restrict__ encW,
                         const float* __restrict__ s2cW, const float* __restrict__ We1,
                         const float* __restrict__ We2,  const float* __restrict__ c2sW,
                         const float* __restrict__ decW)
{
    if (blockIdx.x == 0 && threadIdx.x < EEXP) g_count[threadIdx.x] = 0;
    const size_t f = (size_t)blockIdx.x * 256 + threadIdx.x;
    if (f >= PK_TOT) return;
    if (f < PK_EW) {
        float2 v = *(const float2*)&X[2 * f];
        ((__half2*)g_Xh)[f] = __floats2half2_rn(v.x, v.y);
        return;
    }
    const float* src; uint32_t* dst; size_t local; int N;
    if      (f < PK_SW) { src = encW; dst = g_encWp; local = f - PK_EW; N = HDIM; }
    else if (f < PK_W1) { src = s2cW; dst = g_s2cWp; local = f - PK_SW; N = MDIM; }
    else if (f < PK_W2) { src = We1;  dst = g_We1p;  local = f - PK_W1; N = HHALF; }
    else if (f < PK_CW) { src = We2;  dst = g_We2p;  local = f - PK_W2; N = MDIM; }
    else if (f < PK_DW) { src = c2sW; dst = g_c2sWp; local = f - PK_CW; N = HDIM; }
    else                { src = decW; dst = g_decWp; local = f - PK_DW; N = DDIM; }
    const size_t kp = local / N, n = local % N;
    const float w0 = src[(2 * kp) * (size_t)N + n];
    const float w1 = src[(2 * kp + 1) * (size_t)N + n];
    ((__half2*)dst)[local] = __floats2half2_rn(w0, w1);
}

// ---------------------------------------------------------------------------
// Fused GEMM+GEMM, fp16, BK=64 halfs, 3 stages, ldmatrix A, deferred W2.
//   EXPM=false: enc+s2c.   EXPM=true: expert MLP (gather/scatter).
// ---------------------------------------------------------------------------
template<bool EXPM>
__global__ __launch_bounds__(256, 2)
void fused_gemm2(const __half* __restrict__ A, const uint32_t* __restrict__ W1p,
                 const float* __restrict__ b1, const uint32_t* __restrict__ W2p,
                 float* __restrict__ Cpart, int K, int lda, int ldw1,
                 const int* __restrict__ bucket, const int* __restrict__ count)
{
    extern __shared__ uint32_t smw[];
    uint32_t* w2s   = smw;               // stage-0 region (dead after mainloop)
    uint32_t* spike = smw + SPIKE_OFF;   // stage-1 region

    const int tid = threadIdx.x, lane = tid & 31, w = tid >> 5;
    const int g = lane >> 2, tg = lane & 3;
    const int wm = w >> 2, wn = w & 3;
    const int rowsel = lane & 15;
    const int colsel = (lane >> 4) << 2;
    const int bm0 = blockIdx.y * BM, bn0 = blockIdx.x * BN;
    const int e = EXPM ? blockIdx.z : 0;

    int cnt = 0;
    if (EXPM) {
        cnt = count[e];
        if (bm0 >= cnt) return;
    }

    const uint32_t* W1 = EXPM ? W1p + (size_t)e * (MDIM / 2) * HHALF : W1p;
    const float*    bb = EXPM ? b1 + (size_t)e * HHALF : b1;
    const uint32_t* W2 = EXPM ? W2p + (size_t)e * (HHALF / 2) * MDIM : W2p;

    // A tile: 128 rows x 32 words = 1024 cp16 -> 4/thread (rows tid>>3 + 32*it)
    size_t aoff[4];
#pragma unroll
    for (int it = 0; it < 4; it++) {
        const int r = (tid >> 3) + 32 * it;
        const int grow = bm0 + r;
        if (EXPM) {
            const int rr = (grow < cnt) ? grow : (cnt - 1);
            aoff[it] = (size_t)(bucket[e * ECAP + rr] >> 1) * MDIM;
        } else {
            aoff[it] = (size_t)grow * lda;
        }
    }

    float c[4][4][4];
#pragma unroll
    for (int i = 0; i < 4; i++)
#pragma unroll
        for (int j = 0; j < 4; j++)
#pragma unroll
            for (int q = 0; q < 4; q++) c[i][j][q] = 0.0f;

    const int nk = K / 64;
    auto issue = [&](int st, int kt) {
        const int k0 = kt * 64;                       // halfs
        uint32_t* as = smw + st * STG2_W;
        uint32_t* bs = as + BM * AS2;
#pragma unroll
        for (int it = 0; it < 4; it++) {
            const int r  = (tid >> 3) + 32 * it;
            const int c4 = tid & 7;
            cp16(&as[r * AS2 + c4 * 4], A + aoff[it] + k0 + c4 * 8);
        }
#pragma unroll
        for (int it = 0; it < 4; it++) {
            int idx = tid + it * 256;
            int r = idx >> 5, cc = idx & 31;
            cp16(&bs[r * BS2 + cc * 4],
                 &W1[(size_t)(kt * 32 + r) * ldw1 + bn0 + cc * 4]);
        }
    };

#pragma unroll
    for (int s = 0; s < ST2 - 1; s++) {
        if (s < nk) issue(s, s);
        cp_commit();
    }
    for (int kt = 0; kt < nk; kt++) {
        cp_wait<ST2 - 2>();
        __syncthreads();
        const int st = kt % ST2;
        const uint32_t* as = smw + st * STG2_W;
        const uint32_t* bs = as + BM * AS2;
        const uint32_t as_b = smem_u32(as);
#pragma unroll
        for (int ks = 0; ks < 4; ks++) {
            uint32_t a[4][4], b[4][2];
#pragma unroll
            for (int mf = 0; mf < 4; mf++) {
                const int m0 = wm * 64 + mf * 16;
                ldsm_x4(a[mf], as_b + (((m0 + rowsel) * AS2 + ks * 8 + colsel) << 2));
            }
#pragma unroll
            for (int nf = 0; nf < 4; nf++) {
                const int n0 = wn * 32 + nf * 8 + g;
                b[nf][0] = bs[(ks * 8 + tg)     * BS2 + n0];
                b[nf][1] = bs[(ks * 8 + tg + 4) * BS2 + n0];
            }
#pragma unroll
            for (int mf = 0; mf < 4; mf++)
#pragma unroll
                for (int nf = 0; nf < 4; nf++) mma_f16(c[mf][nf], a[mf], b[nf]);
        }
        const int nxt = kt + ST2 - 1;
        if (nxt < nk) issue(nxt % ST2, nxt);
        cp_commit();
    }

    cp_wait<0>();
    __syncthreads();

    // Deferred W2 chunk load into dead stage-0 region (latency hides under epilogue)
#pragma unroll
    for (int it = 0; it < 4; it++) {
        int idx = tid + it * 256;
        int r = idx >> 4, cc = idx & 15;
        cp16(&w2s[r * W2_S + cc * 4], &W2[(size_t)(bn0 / 2 + r) * MDIM + cc * 4]);
    }
    cp_commit();

    // Activated tile -> spike (stage-1 region) as half2 words
#pragma unroll
    for (int mf = 0; mf < 4; mf++)
#pragma unroll
        for (int nf = 0; nf < 4; nf++) {
            const int col = wn * 32 + nf * 8 + 2 * tg;
            const int r0  = wm * 64 + mf * 16 + g;
#pragma unroll
            for (int h = 0; h < 2; h++) {
                const int row = r0 + h * 8;
                float v0 = c[mf][nf][h * 2 + 0] + bb[bn0 + col];
                float v1 = c[mf][nf][h * 2 + 1] + bb[bn0 + col + 1];
                if (EXPM) { v0 = fmaxf(v0, 0.0f); v1 = fmaxf(v1, 0.0f); }
                else      { v0 = sigf(v0);        v1 = sigf(v1); }
                spike[row * SPIKE_S + (col >> 1)] = h2u(v0, v1);
            }
        }
    cp_wait<0>();
    __syncthreads();

    // mini GEMM: part[128x64] = spike(128x128 halfs) @ w2s
    const int wm2 = w >> 1, wn2 = w & 1;
    const uint32_t spike_b = smem_u32(spike);
    float c2[2][4][4];
#pragma unroll
    for (int i = 0; i < 2; i++)
#pragma unroll
        for (int j = 0; j < 4; j++)
#pragma unroll
            for (int q = 0; q < 4; q++) c2[i][j][q] = 0.0f;
#pragma unroll
    for (int s = 0; s < 8; s++) {
        uint32_t a[2][4], b[4][2];
#pragma unroll
        for (int mf = 0; mf < 2; mf++) {
            const int m0 = wm2 * 32 + mf * 16;
            ldsm_x4(a[mf], spike_b + (((m0 + rowsel) * SPIKE_S + s * 8 + colsel) << 2));
        }
#pragma unroll
        for (int nf = 0; nf < 4; nf++) {
            const int n0 = wn2 * 32 + nf * 8 + g;
            b[nf][0] = w2s[(s * 8 + tg)     * W2_S + n0];
            b[nf][1] = w2s[(s * 8 + tg + 4) * W2_S + n0];
        }
#pragma unroll
        for (int mf = 0; mf < 2; mf++)
#pragma unroll
            for (int nf = 0; nf < 4; nf++) mma_f16(c2[mf][nf], a[mf], b[nf]);
    }
    const size_t sb = (size_t)blockIdx.x * (EXPM ? NASSIGN : NTOK) * MDIM;
#pragma unroll
    for (int mf = 0; mf < 2; mf++)
#pragma unroll
        for (int nf = 0; nf < 4; nf++) {
            const int col = wn2 * 32 + nf * 8 + 2 * tg;
            const int r0  = wm2 * 32 + mf * 16 + g;
#pragma unroll
            for (int h = 0; h < 2; h++) {
                const int row = r0 + h * 8;
                if (EXPM) {
                    if (bm0 + row < cnt) {
                        const int i = bucket[e * ECAP + bm0 + row];
                        *(float2*)&Cpart[sb + (size_t)i * MDIM + col] =
                            make_float2(c2[mf][nf][h * 2 + 0], c2[mf][nf][h * 2 + 1]);
                    }
                } else {
                    *(float2*)&Cpart[sb + (size_t)(bm0 + row) * MDIM + col] =
                        make_float2(c2[mf][nf][h * 2 + 0], c2[mf][nf][h * 2 + 1]);
                }
            }
        }
}

// ---------------------------------------------------------------------------
// Plain GEMM BK=64 halfs, 3 stages, ldmatrix A. MODE 0: dec. MODE 1: c2s.
// ---------------------------------------------------------------------------
template<int MODE>
__global__ __launch_bounds__(256, 2)
void mma_gemm(const __half* __restrict__ A, const uint32_t* __restrict__ Wp,
              const float* __restrict__ bias, void* __restrict__ Cv,
              int K, int Hout)
{
    extern __shared__ uint32_t smw[];
    const int tid = threadIdx.x, lane = tid & 31, w = tid >> 5;
    const int g = lane >> 2, tg = lane & 3;
    const int wm = w >> 2, wn = w & 3;
    const int rowsel = lane & 15;
    const int colsel = (lane >> 4) << 2;
    const int bm0 = blockIdx.y * BM, bn0 = blockIdx.x * BN;

    float c[4][4][4];
#pragma unroll
    for (int i = 0; i < 4; i++)
#pragma unroll
        for (int j = 0; j < 4; j++)
#pragma unroll
            for (int q = 0; q < 4; q++) c[i][j][q] = 0.0f;

    const int nk = K / 64;
    auto issue = [&](int st, int kt) {
        const int k0 = kt * 64;
        uint32_t* as = smw + st * STG2_W;
        uint32_t* bs = as + BM * AS2;
#pragma unroll
        for (int it = 0; it < 4; it++) {
            int idx = tid + it * 256;
            int r = idx >> 3, c4 = idx & 7;
            cp16(&as[r * AS2 + c4 * 4], A + (size_t)(bm0 + r) * K + k0 + c4 * 8);
        }
#pragma unroll
        for (int it = 0; it < 4; it++) {
            int idx = tid + it * 256;
            int r = idx >> 5, cc = idx & 31;
            cp16(&bs[r * BS2 + cc * 4],
                 &Wp[(size_t)(kt * 32 + r) * Hout + bn0 + cc * 4]);
        }
    };

#pragma unroll
    for (int s = 0; s < ST2 - 1; s++) {
        if (s < nk) issue(s, s);
        cp_commit();
    }
    for (int kt = 0; kt < nk; kt++) {
        cp_wait<ST2 - 2>();
        __syncthreads();
        const int st = kt % ST2;
        const uint32_t* as = smw + st * STG2_W;
        const uint32_t* bs = as + BM * AS2;
        const uint32_t as_b = smem_u32(as);
#pragma unroll
        for (int ks = 0; ks < 4; ks++) {
            uint32_t a[4][4], b[4][2];
#pragma unroll
            for (int mf = 0; mf < 4; mf++) {
                const int m0 = wm * 64 + mf * 16;
                ldsm_x4(a[mf], as_b + (((m0 + rowsel) * AS2 + ks * 8 + colsel) << 2));
            }
#pragma unroll
            for (int nf = 0; nf < 4; nf++) {
                const int n0 = wn * 32 + nf * 8 + g;
                b[nf][0] = bs[(ks * 8 + tg)     * BS2 + n0];
                b[nf][1] = bs[(ks * 8 + tg + 4) * BS2 + n0];
            }
#pragma unroll
            for (int mf = 0; mf < 4; mf++)
#pragma unroll
                for (int nf = 0; nf < 4; nf++) mma_f16(c[mf][nf], a[mf], b[nf]);
        }
        const int nxt = kt + ST2 - 1;
        if (nxt < nk) issue(nxt % ST2, nxt);
        cp_commit();
    }

#pragma unroll
    for (int mf = 0; mf < 4; mf++)
#pragma unroll
        for (int nf = 0; nf < 4; nf++) {
            const int col = bn0 + wn * 32 + nf * 8 + 2 * tg;
            const int r0  = bm0 + wm * 64 + mf * 16 + g;
#pragma unroll
            for (int h = 0; h < 2; h++) {
                const int row = r0 + h * 8;
                float v0 = sigf(c[mf][nf][h * 2 + 0] + bias[col]);
                float v1 = sigf(c[mf][nf][h * 2 + 1] + bias[col + 1]);
                if (MODE == 1) {
                    ((uint32_t*)Cv)[(size_t)row * (Hout / 2) + (col >> 1)] = h2u(v0, v1);
                } else {
                    *(float2*)&((float*)Cv)[(size_t)row * Hout + col] = make_float2(v0, v1);
                }
            }
        }
}

// ---------------------------------------------------------------------------
// Router: one warp per token, __syncwarp only (bit-same gates).
// ---------------------------------------------------------------------------
__global__ void router_kernel(const float* __restrict__ part_s2c,
                              const float* __restrict__ s2c_b,
                              __half* __restrict__ cont,
                              const float* __restrict__ rW1, const float* __restrict__ rb1,
                              const float* __restrict__ rW2, const float* __restrict__ rb2,
                              int* __restrict__ assign_e, float* __restrict__ assign_w)
{
    __shared__ float cs[4][64], hid[4][64], logit[4][8];
    const int wid = threadIdx.x >> 5, lane = threadIdx.x & 31;
    const int n = blockIdx.x * 4 + wid;

#pragma unroll
    for (int j = 0; j < 2; j++) {
        const int t = lane + 32 * j;
        float cv = s2c_b[t];
#pragma unroll
        for (int s = 0; s < S2C_SPLIT; s++)
            cv += part_s2c[(size_t)s * NTOK * MDIM + (size_t)n * MDIM + t];
        cont[(size_t)n * MDIM + t] = __float2half_rn(cv);
        cs[wid][t] = cv;
    }
    __syncwarp();

#pragma unroll
    for (int j = 0; j < 2; j++) {
        const int t = lane + 32 * j;
        float a = rb1[t];
#pragma unroll
        for (int m = 0; m < 64; m++) a = fmaf(cs[wid][m], rW1[m * 64 + t], a);
        hid[wid][t] = tanhf(a);
    }
    __syncwarp();

    if (lane < EEXP) {
        float l = rb2[lane];
#pragma unroll
        for (int j = 0; j < 64; j++) l = fmaf(hid[wid][j], rW2[j * EEXP + lane], l);
        logit[wid][lane] = l;
    }
    __syncwarp();

    if (lane == 0) {
        float mx = logit[wid][0];
        for (int e = 1; e < EEXP; e++) mx = fmaxf(mx, logit[wid][e]);
        float p[EEXP];
        for (int e = 0; e < EEXP; e++) p[e] = expf(logit[wid][e] - mx);
        int i1 = 0;
        for (int e = 1; e < EEXP; e++) if (p[e] > p[i1]) i1 = e;
        int i2 = (i1 == 0) ? 1 : 0;
        for (int e = 0; e < EEXP; e++) if (e != i1 && p[e] > p[i2]) i2 = e;
        const float denom = p[i1] + p[i2];
        const int ids[2] = {i1, i2};
        const float ws[2] = {p[i1] / denom, p[i2] / denom};
#pragma unroll
        for (int k = 0; k < 2; k++) {
            const int i = n * 2 + k;
            assign_e[i] = ids[k];
            assign_w[i] = ws[k];
            const int slot = atomicAdd(&g_count[ids[k]], 1);
            g_bucket[ids[k] * ECAP + slot] = i;
        }
    }
}

__global__ void combine_kernel(const float* __restrict__ part_exp,
                               const int* __restrict__ ae, const float* __restrict__ aw,
                               const float* __restrict__ be2, __half* __restrict__ outflat)
{
    const int i = blockIdx.x * 256 + threadIdx.x;
    const int n = i >> 6, m = i & 63;
    float acc = 0.0f;
#pragma unroll
    for (int k = 0; k < 2; k++) {
        const int idx = 2 * n + k;
        float s = be2[ae[idx] * MDIM + m];
#pragma unroll
        for (int sp = 0; sp < EXP_SPLIT; sp++)
            s += part_exp[(size_t)sp * NASSIGN * MDIM + (size_t)idx * MDIM + m];
        acc = fmaf(aw[idx], s, acc);
    }
    outflat[i] = __float2half_rn(acc);
}

__global__ void layernorm_kernel(const float* __restrict__ x,
                                 const float* __restrict__ g, const float* __restrict__ b,
                                 float* __restrict__ out)
{
    const int n = blockIdx.x, t = threadIdx.x;
    const float* row = x + (size_t)n * DDIM;
    float v[4];
    float s = 0.0f, s2 = 0.0f;
#pragma unroll
    for (int i = 0; i < 4; i++) {
        v[i] = row[t + i * 256];
        s += v[i]; s2 += v[i] * v[i];
    }
#pragma unroll
    for (int o = 16; o > 0; o >>= 1) {
        s  += __shfl_xor_sync(0xFFFFFFFFu, s, o);
        s2 += __shfl_xor_sync(0xFFFFFFFFu, s2, o);
    }
    __shared__ float sh1[8], sh2[8], mu_s, rstd_s;
    const int warp = t >> 5, lane = t & 31;
    if (lane == 0) { sh1[warp] = s; sh2[warp] = s2; }
    __syncthreads();
    if (t == 0) {
        float S = 0.0f, S2 = 0.0f;
        for (int wq = 0; wq < 8; wq++) { S += sh1[wq]; S2 += sh2[wq]; }
        float mu = S / (float)DDIM;
        mu_s = mu;
        rstd_s = rsqrtf(S2 / (float)DDIM - mu * mu + 1e-5f);
    }
    __syncthreads();
    const float mu = mu_s, rstd = rstd_s;
    float* orow = out + (size_t)n * DDIM;
#pragma unroll
    for (int i = 0; i < 4; i++) {
        int col = t + i * 256;
        orow[col] = (v[i] - mu) * rstd * g[col] + b[col];
    }
}

// ---------------------------------------------------------------------------
extern "C" void kernel_launch(void* const* d_in, const int* in_sizes, int n_in,
                              void* d_out, int out_size)
{
    const float* X     = (const float*)d_in[0];
    const float* enc_W = (const float*)d_in[1];
    const float* enc_b = (const float*)d_in[2];
    const float* s2c_W = (const float*)d_in[3];
    const float* s2c_b = (const float*)d_in[4];
    const float* rW1   = (const float*)d_in[5];
    const float* rb1   = (const float*)d_in[6];
    const float* rW2   = (const float*)d_in[7];
    const float* rb2   = (const float*)d_in[8];
    const float* We1   = (const float*)d_in[9];
    const float* be1   = (const float*)d_in[10];
    const float* We2   = (const float*)d_in[11];
    const float* be2   = (const float*)d_in[12];
    const float* c2s_W = (const float*)d_in[13];
    const float* c2s_b = (const float*)d_in[14];
    const float* dec_W = (const float*)d_in[15];
    const float* dec_b = (const float*)d_in[16];
    const float* ln_g  = (const float*)d_in[17];
    const float* ln_b  = (const float*)d_in[18];

    __half *Xh, *cont, *outflat, *spk_moe;
    uint32_t *encWp, *s2cWp, *We1p, *We2p, *c2sWp, *decWp;
    float *part_s2c, *aw, *part_exp, *decoded;
    int *ae, *bucket, *count;
    cudaGetSymbolAddress((void**)&Xh,       g_Xh);
    cudaGetSymbolAddress((void**)&encWp,    g_encWp);
    cudaGetSymbolAddress((void**)&s2cWp,    g_s2cWp);
    cudaGetSymbolAddress((void**)&We1p,     g_We1p);
    cudaGetSymbolAddress((void**)&We2p,     g_We2p);
    cudaGetSymbolAddress((void**)&c2sWp,    g_c2sWp);
    cudaGetSymbolAddress((void**)&decWp,    g_decWp);
    cudaGetSymbolAddress((void**)&part_s2c, g_part_s2c);
    cudaGetSymbolAddress((void**)&cont,     g_cont);
    cudaGetSymbolAddress((void**)&ae,       g_assign_e);
    cudaGetSymbolAddress((void**)&aw,       g_assign_w);
    cudaGetSymbolAddress((void**)&count,    g_count);
    cudaGetSymbolAddress((void**)&bucket,   g_bucket);
    cudaGetSymbolAddress((void**)&part_exp, g_part_exp);
    cudaGetSymbolAddress((void**)&outflat,  g_outflat);
    cudaGetSymbolAddress((void**)&spk_moe,  g_spk_moe);
    cudaGetSymbolAddress((void**)&decoded,  g_decoded);

    auto kEnc = fused_gemm2<false>;
    auto kExp = fused_gemm2<true>;
    auto kC2s = mma_gemm<1>;
    auto kDec = mma_gemm<0>;
    cudaFuncSetAttribute(kEnc, cudaFuncAttributeMaxDynamicSharedMemorySize, PIPE2_SMEM);
    cudaFuncSetAttribute(kExp, cudaFuncAttributeMaxDynamicSharedMemorySize, PIPE2_SMEM);
    cudaFuncSetAttribute(kC2s, cudaFuncAttributeMaxDynamicSharedMemorySize, PIPE2_SMEM);
    cudaFuncSetAttribute(kDec, cudaFuncAttributeMaxDynamicSharedMemorySize, PIPE2_SMEM);

    // 0) prep: fp16 conversion + k-pair packing + zero counts
    prep_all<<<(PK_TOT + 255) / 256, 256>>>(X, enc_W, s2c_W, We1, We2, c2s_W, dec_W);

    // 1) fused encoder+s2c (K=1024 halfs, 16 K-tiles)
    kEnc<<<dim3(S2C_SPLIT, NTOK / BM), 256, PIPE2_SMEM>>>(
        Xh, encWp, enc_b, s2cWp, part_s2c, DDIM, DDIM, HDIM, nullptr, nullptr);

    // 2) routing (warp per token)
    router_kernel<<<NTOK / 4, 128>>>(part_s2c, s2c_b, cont, rW1, rb1, rW2, rb2, ae, aw);

    // 3) fused expert MLP (K=64 halfs, single K-tile)
    kExp<<<dim3(EXP_SPLIT, ECAP / BM, EEXP), 256, PIPE2_SMEM>>>(
        cont, We1p, be1, We2p, part_exp, MDIM, MDIM, HHALF, bucket, count);

    // 4) combine
    combine_kernel<<<(NTOK * MDIM) / 256, 256>>>(part_exp, ae, aw, be2, outflat);

    // 5) c2s: sigmoid -> half spk_moe (K=64, single K-tile)
    kC2s<<<dim3(HDIM / BN, NTOK / BM), 256, PIPE2_SMEM>>>(
        outflat, c2sWp, c2s_b, spk_moe, MDIM, HDIM);

    // 6) decoder: sigmoid -> fp32 decoded (K=2048, 32 K-tiles)
    kDec<<<dim3(DDIM / BN, NTOK / BM), 256, PIPE2_SMEM>>>(
        spk_moe, decWp, dec_b, decoded, HDIM, DDIM);

    // 7) layernorm -> d_out
    layernorm_kernel<<<NTOK, 256>>>(decoded, ln_g, ln_b, (float*)d_out);
}